// round 2
// baseline (speedup 1.0000x reference)
#include <cuda_runtime.h>
#include <cuda_bf16.h>
#include <cstdint>

#define NCOMP 16384
#define NSEC 64
#define PERSEC 256
#define WIN 32
#define DIN 16
#define HG 64
#define G3 192

// ---------------- scratch (device globals; no allocation) ----------------
__device__ float g_scale[WIN * DIN];
__device__ float g_shift[WIN * DIN];
__device__ float g_Wp[WIN * DIN * G3];
__device__ float g_bp[WIN * G3];
__device__ float g_seq[NCOMP * HG];     // GRU final hidden
__device__ float g_h1[NCOMP * HG];      // GAT1 transformed
__device__ float g_ssrc[NCOMP];
__device__ float g_sdst[NCOMP];
__device__ unsigned g_maxkey[NCOMP];
__device__ float g_denom[NCOMP];
__device__ float g_num[NCOMP * HG];
__device__ float g_intra[NCOMP * HG];
__device__ float g_pool[NSEC * HG];
__device__ float g_sec[NSEC * HG];

// ---------------- helpers ----------------
__device__ __forceinline__ float4 ld4(const float* p) { return *(const float4*)p; }
__device__ __forceinline__ void st4(float* p, float4 v) { *(float4*)p = v; }
__device__ __forceinline__ void fma4(float4& a, float s, float4 b) {
    a.x = fmaf(s, b.x, a.x); a.y = fmaf(s, b.y, a.y);
    a.z = fmaf(s, b.z, a.z); a.w = fmaf(s, b.w, a.w);
}
__device__ __forceinline__ float4 add4(float4 a, float4 b) {
    return make_float4(a.x + b.x, a.y + b.y, a.z + b.z, a.w + b.w);
}
// order-preserving float<->uint for atomicMax on possibly-negative floats
__device__ __forceinline__ unsigned fenc(float f) {
    unsigned u = __float_as_uint(f);
    return (u & 0x80000000u) ? ~u : (u | 0x80000000u);
}
__device__ __forceinline__ float fdec(unsigned k) {
    return (k & 0x80000000u) ? __uint_as_float(k ^ 0x80000000u) : __uint_as_float(~k);
}
__device__ __forceinline__ float lrelu(float v) { return v > 0.f ? v : 0.2f * v; }

// ---------------- K1: BN stats -> scale/shift ----------------
__global__ void k_bn_stats(const float* __restrict__ daily,
                           const float* __restrict__ gamma,
                           const float* __restrict__ beta) {
    int w = blockIdx.x;
    int t = threadIdx.x, lane = t & 31, wid = t >> 5;
    float s[DIN], q[DIN];
#pragma unroll
    for (int d = 0; d < DIN; d++) { s[d] = 0.f; q[d] = 0.f; }
    const float4* base = (const float4*)(daily + (size_t)w * NCOMP * DIN);
    for (int n = t; n < NCOMP; n += 256) {
        float4 vv[4];
        vv[0] = base[n * 4 + 0]; vv[1] = base[n * 4 + 1];
        vv[2] = base[n * 4 + 2]; vv[3] = base[n * 4 + 3];
        const float* v = (const float*)vv;
#pragma unroll
        for (int d = 0; d < DIN; d++) { s[d] += v[d]; q[d] += v[d] * v[d]; }
    }
#pragma unroll
    for (int d = 0; d < DIN; d++) {
        for (int o = 16; o; o >>= 1) {
            s[d] += __shfl_down_sync(0xffffffffu, s[d], o);
            q[d] += __shfl_down_sync(0xffffffffu, q[d], o);
        }
    }
    __shared__ float S[8][DIN], Q[8][DIN];
    if (lane == 0) {
#pragma unroll
        for (int d = 0; d < DIN; d++) { S[wid][d] = s[d]; Q[wid][d] = q[d]; }
    }
    __syncthreads();
    if (t < DIN) {
        float ts = 0.f, tq = 0.f;
#pragma unroll
        for (int r = 0; r < 8; r++) { ts += S[r][t]; tq += Q[r][t]; }
        float mu = ts * (1.f / (float)NCOMP);
        float var = tq * (1.f / (float)NCOMP) - mu * mu;
        int f = w * DIN + t;
        float sc = gamma[f] * rsqrtf(var + 1e-5f);
        g_scale[f] = sc;
        g_shift[f] = beta[f] - mu * sc;
    }
}

// ---------------- K2: folded input-projection weights ----------------
__global__ void k_build_wp(const float* __restrict__ Wih,
                           const float* __restrict__ bih) {
    int w = blockIdx.x;
    int j = threadIdx.x; // 192
    float bp = bih[j];
#pragma unroll
    for (int d = 0; d < DIN; d++) {
        float wij = Wih[d * G3 + j];
        g_Wp[((size_t)w * DIN + d) * G3 + j] = g_scale[w * DIN + d] * wij;
        bp += g_shift[w * DIN + d] * wij;
    }
    g_bp[w * G3 + j] = bp;
}

// ---------------- K3: fused persistent GRU ----------------
// grid 512 blocks x 256 threads; block owns 32 companies; thread = (ci, g):
// ci = company-in-block, g = 8-wide j-slice of the 64 hidden dims.
#define SM3_FLOATS (12288 + 3072 + 192 + 192 + 2 * 32 * 65 + 32 * 17)
__global__ void k_gru(const float* __restrict__ daily,
                      const float* __restrict__ Whh,
                      const float* __restrict__ bhh,
                      const float* __restrict__ h0) {
    extern __shared__ float sm[];
    float* Whh_s = sm;                // 64*192
    float* Wp_s  = sm + 12288;        // 16*192
    float* bp_s  = sm + 15360;        // 192
    float* bhh_s = sm + 15552;        // 192
    float* h_buf = sm + 15744;        // [2][32][65]
    float* x_s   = sm + 15744 + 2 * 32 * 65; // [32][17]
    int t = threadIdx.x;
    int ci = t & 31, g = t >> 5;
    int c0 = blockIdx.x * 32;

    {
        const float4* W4 = (const float4*)Whh;
        float4* Ws4 = (float4*)Whh_s;
        for (int i = t; i < 3072; i += 256) Ws4[i] = W4[i];
        if (t < G3) bhh_s[t] = bhh[t];
        for (int i = t; i < 32 * HG; i += 256) {
            int cc = i >> 6, k = i & 63;
            h_buf[cc * 65 + k] = h0[(size_t)(c0 + cc) * HG + k];
        }
    }
    __syncthreads();

    int cur = 0;
    int j0 = g * 8;
    for (int w = 0; w < WIN; w++) {
        // stage per-step W', b', x
        {
            const float4* Wp4 = (const float4*)(g_Wp + (size_t)w * DIN * G3);
            float4* Wd4 = (float4*)Wp_s;
            for (int i = t; i < 768; i += 256) Wd4[i] = Wp4[i];
            if (t < G3) bp_s[t] = g_bp[w * G3 + t];
            for (int i = t; i < 32 * DIN; i += 256) {
                int cc = i >> 4, d = i & 15;
                x_s[cc * 17 + d] = daily[((size_t)w * NCOMP + c0 + cc) * DIN + d];
            }
        }
        __syncthreads();

        float* h  = h_buf + cur * 2080 + ci * 65;
        float* hn = h_buf + (cur ^ 1) * 2080 + ci * 65;

        float4 aR0 = add4(ld4(bp_s + j0), ld4(bhh_s + j0));
        float4 aR1 = add4(ld4(bp_s + j0 + 4), ld4(bhh_s + j0 + 4));
        float4 aZ0 = add4(ld4(bp_s + 64 + j0), ld4(bhh_s + 64 + j0));
        float4 aZ1 = add4(ld4(bp_s + 64 + j0 + 4), ld4(bhh_s + 64 + j0 + 4));
        float4 aNi0 = ld4(bp_s + 128 + j0);
        float4 aNi1 = ld4(bp_s + 128 + j0 + 4);
        float4 aNh0 = ld4(bhh_s + 128 + j0);
        float4 aNh1 = ld4(bhh_s + 128 + j0 + 4);

#pragma unroll
        for (int d = 0; d < DIN; d++) {
            float xd = x_s[ci * 17 + d];
            const float* row = Wp_s + d * G3 + j0;
            fma4(aR0, xd, ld4(row));        fma4(aR1, xd, ld4(row + 4));
            fma4(aZ0, xd, ld4(row + 64));   fma4(aZ1, xd, ld4(row + 68));
            fma4(aNi0, xd, ld4(row + 128)); fma4(aNi1, xd, ld4(row + 132));
        }
#pragma unroll 8
        for (int k = 0; k < HG; k++) {
            float hk = h[k];
            const float* row = Whh_s + k * G3 + j0;
            fma4(aR0, hk, ld4(row));        fma4(aR1, hk, ld4(row + 4));
            fma4(aZ0, hk, ld4(row + 64));   fma4(aZ1, hk, ld4(row + 68));
            fma4(aNh0, hk, ld4(row + 128)); fma4(aNh1, hk, ld4(row + 132));
        }
        // activations for 8 outputs
        {
            float R[8] = {aR0.x, aR0.y, aR0.z, aR0.w, aR1.x, aR1.y, aR1.z, aR1.w};
            float Z[8] = {aZ0.x, aZ0.y, aZ0.z, aZ0.w, aZ1.x, aZ1.y, aZ1.z, aZ1.w};
            float Ni[8] = {aNi0.x, aNi0.y, aNi0.z, aNi0.w, aNi1.x, aNi1.y, aNi1.z, aNi1.w};
            float Nh[8] = {aNh0.x, aNh0.y, aNh0.z, aNh0.w, aNh1.x, aNh1.y, aNh1.z, aNh1.w};
#pragma unroll
            for (int jj = 0; jj < 8; jj++) {
                float r = 1.f / (1.f + __expf(-R[jj]));
                float z = 1.f / (1.f + __expf(-Z[jj]));
                float n = tanhf(fmaf(r, Nh[jj], Ni[jj]));
                float hold = h[j0 + jj];
                hn[j0 + jj] = fmaf(z, hold - n, n);
            }
        }
        __syncthreads();
        cur ^= 1;
    }
    // writeout
    float* hf = h_buf + cur * 2080;
    for (int i = t; i < 32 * HG; i += 256) {
        int cc = i >> 6, k = i & 63;
        g_seq[(size_t)(c0 + cc) * HG + k] = hf[cc * 65 + k];
    }
}

// ---------------- K4: GAT1 node transform + attention dots + init ----------------
__global__ void k_gat1_node(const float* __restrict__ W1,
                            const float* __restrict__ a1s,
                            const float* __restrict__ a1d) {
    __shared__ float W1s[HG * HG];
    __shared__ float xs[64 * 65];
    __shared__ float as_s[HG], ad_s[HG];
    int t = threadIdx.x;
    int c0 = blockIdx.x * 64;
    for (int i = t; i < HG * HG; i += 256) W1s[i] = W1[i];
    for (int i = t; i < 64 * HG; i += 256) {
        int cc = i >> 6, k = i & 63;
        xs[cc * 65 + k] = g_seq[(size_t)(c0 + cc) * HG + k];
    }
    if (t < HG) { as_s[t] = a1s[t]; ad_s[t] = a1d[t]; }
    __syncthreads();

    int cl = t >> 2, q = t & 3, c = c0 + cl;
    float4 acc[4] = {make_float4(0,0,0,0), make_float4(0,0,0,0),
                     make_float4(0,0,0,0), make_float4(0,0,0,0)};
#pragma unroll 8
    for (int k = 0; k < HG; k++) {
        float x = xs[cl * 65 + k];
        const float* row = W1s + k * HG + q * 16;
#pragma unroll
        for (int u = 0; u < 4; u++) fma4(acc[u], x, ld4(row + 4 * u));
    }
    float ps = 0.f, pd = 0.f;
#pragma unroll
    for (int u = 0; u < 4; u++) {
        int jb = q * 16 + 4 * u;
        const float* a = (const float*)&acc[u];
#pragma unroll
        for (int e = 0; e < 4; e++) {
            ps += a[e] * as_s[jb + e];
            pd += a[e] * ad_s[jb + e];
        }
        st4(g_h1 + (size_t)c * HG + jb, acc[u]);
        st4(g_num + (size_t)c * HG + jb, make_float4(0, 0, 0, 0));
    }
    ps += __shfl_xor_sync(0xffffffffu, ps, 1);
    ps += __shfl_xor_sync(0xffffffffu, ps, 2);
    pd += __shfl_xor_sync(0xffffffffu, pd, 1);
    pd += __shfl_xor_sync(0xffffffffu, pd, 2);
    if (q == 0) {
        g_ssrc[c] = ps; g_sdst[c] = pd;
        g_maxkey[c] = 0u; g_denom[c] = 0.f;
    }
}

// ---------------- K5: edge softmax max pass ----------------
__global__ void k_edge_max(const int* __restrict__ edges, int E) {
    int idx = blockIdx.x * 256 + threadIdx.x;
    int TOT = E + NCOMP;
    if (idx >= TOT) return;
    int src, dst;
    if (idx < E) { src = edges[idx]; dst = edges[E + idx]; }
    else { src = dst = idx - E; }
    float e = lrelu(g_ssrc[src] + g_sdst[dst]);
    atomicMax(&g_maxkey[dst], fenc(e));
}

// ---------------- K6: edge accumulate pass (warp per edge) ----------------
__global__ void k_edge_acc(const int* __restrict__ edges, int E) {
    int gt = blockIdx.x * 256 + threadIdx.x;
    int gw = gt >> 5, lane = gt & 31;
    int TOT = E + NCOMP;
    if (gw >= TOT) return;
    int src, dst;
    if (gw < E) { src = edges[gw]; dst = edges[E + gw]; }
    else { src = dst = gw - E; }
    float e = lrelu(g_ssrc[src] + g_sdst[dst]);
    float m = fdec(g_maxkey[dst]);
    float wexp = __expf(e - m);
    if (lane == 0) atomicAdd(&g_denom[dst], wexp);
    const float* hs = g_h1 + (size_t)src * HG;
    float* np = g_num + (size_t)dst * HG;
    atomicAdd(np + lane, wexp * hs[lane]);
    atomicAdd(np + lane + 32, wexp * hs[lane + 32]);
}

// ---------------- K7: finalize GAT1 ----------------
__global__ void k_gat1_fin(const float* __restrict__ b1) {
    int idx = blockIdx.x * 256 + threadIdx.x;
    int c = idx >> 6, j = idx & 63;
    g_intra[idx] = g_num[idx] / (g_denom[c] + 1e-16f) + b1[j];
}

// ---------------- K7b: sector max pool ----------------
__global__ void k_pool() {
    int s = blockIdx.x;
    int tx = threadIdx.x, ty = threadIdx.y;
    float m = -3.4e38f;
    for (int cc = ty; cc < PERSEC; cc += 4)
        m = fmaxf(m, g_intra[((size_t)(s * PERSEC + cc)) * HG + tx]);
    __shared__ float red[4][64];
    red[ty][tx] = m;
    __syncthreads();
    if (ty == 0) {
        m = fmaxf(fmaxf(red[0][tx], red[1][tx]), fmaxf(red[2][tx], red[3][tx]));
        g_pool[s * HG + tx] = m;
    }
}

// ---------------- K8: GAT2 on 64 sectors (dense) — single block ----------------
__global__ void k_gat2(const float* __restrict__ W2,
                       const float* __restrict__ a2s,
                       const float* __restrict__ a2d,
                       const float* __restrict__ b2) {
    __shared__ float W2s[HG * HG];      // reused as alpha after phase B
    __shared__ float h2s[64 * 68];
    __shared__ float ss[64], sd[64], as_s[64], ad_s[64];
    int t = threadIdx.x;
    for (int i = t; i < HG * HG; i += 256) W2s[i] = W2[i];
    if (t < 64) { as_s[t] = a2s[t]; ad_s[t] = a2d[t]; }
    __syncthreads();

    int i = t >> 2, q = t & 3;
    {
        float4 acc[4] = {make_float4(0,0,0,0), make_float4(0,0,0,0),
                         make_float4(0,0,0,0), make_float4(0,0,0,0)};
        for (int k = 0; k < HG; k++) {
            float x = g_pool[i * HG + k];
            const float* row = W2s + k * HG + q * 16;
#pragma unroll
            for (int u = 0; u < 4; u++) fma4(acc[u], x, ld4(row + 4 * u));
        }
#pragma unroll
        for (int u = 0; u < 4; u++) st4(h2s + i * 68 + q * 16 + 4 * u, acc[u]);
    }
    __syncthreads();
    if (t < 64) {
        float s1 = 0.f, s2 = 0.f;
        for (int k = 0; k < HG; k++) {
            float v = h2s[t * 68 + k];
            s1 += v * as_s[k]; s2 += v * ad_s[k];
        }
        ss[t] = s1; sd[t] = s2;
    }
    __syncthreads();
    // alpha (overwrite W2s)
    {
        int wi = t >> 5, lane = t & 31;
        for (int dst = wi; dst < 64; dst += 8) {
            float e1 = lrelu(ss[lane] + sd[dst]);
            float e2 = lrelu(ss[lane + 32] + sd[dst]);
            float m = fmaxf(e1, e2);
            for (int o = 16; o; o >>= 1) m = fmaxf(m, __shfl_xor_sync(0xffffffffu, m, o));
            float w1 = __expf(e1 - m), w2 = __expf(e2 - m);
            float s = w1 + w2;
            for (int o = 16; o; o >>= 1) s += __shfl_xor_sync(0xffffffffu, s, o);
            float inv = 1.f / (s + 1e-16f);
            W2s[dst * 64 + lane] = w1 * inv;
            W2s[dst * 64 + lane + 32] = w2 * inv;
        }
    }
    __syncthreads();
    {
        int dst = i;
        float4 o[4] = {make_float4(0,0,0,0), make_float4(0,0,0,0),
                       make_float4(0,0,0,0), make_float4(0,0,0,0)};
        for (int src = 0; src < 64; src++) {
            float a = W2s[dst * 64 + src];
            const float* row = h2s + src * 68 + q * 16;
#pragma unroll
            for (int u = 0; u < 4; u++) fma4(o[u], a, ld4(row + 4 * u));
        }
#pragma unroll
        for (int u = 0; u < 4; u++) {
            int jb = q * 16 + 4 * u;
            float4 v = o[u];
            v.x += b2[jb]; v.y += b2[jb + 1]; v.z += b2[jb + 2]; v.w += b2[jb + 3];
            st4(g_sec + dst * HG + jb, v);
        }
    }
}

// ---------------- K9: fusion + logits + softmax/cumsum/clip ----------------
#define SM9_FLOATS (12288 + 64 * 68 + 256 + 4 + 64)
__global__ void k_fusion(const int* __restrict__ sector_ids,
                         const float* __restrict__ Wf,
                         const float* __restrict__ fb,
                         const float* __restrict__ lw,
                         const float* __restrict__ lb,
                         float* __restrict__ out) {
    extern __shared__ float sm[];
    float* Wfs = sm;                 // 192*64
    float* fs  = sm + 12288;         // 64*68
    float* lws = sm + 12288 + 64 * 68;   // 64*4
    float* lbs = lws + 256;          // 4
    float* fbs = lbs + 4;            // 64
    int t = threadIdx.x;
    int c0 = blockIdx.x * 64;
    {
        const float4* w4 = (const float4*)Wf;
        float4* d4 = (float4*)Wfs;
        for (int i = t; i < 3072; i += 256) d4[i] = w4[i];
        if (t < 256) lws[t] = lw[t];
        if (t < 4) lbs[t] = lb[t];
        if (t < 64) fbs[t] = fb[t];
    }
    __syncthreads();

    int cl = t >> 2, q = t & 3, c = c0 + cl;
    int sec = sector_ids[c];
    const float* x1 = g_seq + (size_t)c * HG;
    const float* x2 = g_sec + (size_t)sec * HG;
    const float* x3 = g_intra + (size_t)c * HG;
    float4 acc[4] = {make_float4(0,0,0,0), make_float4(0,0,0,0),
                     make_float4(0,0,0,0), make_float4(0,0,0,0)};
#pragma unroll 4
    for (int k = 0; k < HG; k++) {
        float xk = x1[k];
        const float* row = Wfs + k * HG + q * 16;
#pragma unroll
        for (int u = 0; u < 4; u++) fma4(acc[u], xk, ld4(row + 4 * u));
    }
#pragma unroll 4
    for (int k = 0; k < HG; k++) {
        float xk = x2[k];
        const float* row = Wfs + (64 + k) * HG + q * 16;
#pragma unroll
        for (int u = 0; u < 4; u++) fma4(acc[u], xk, ld4(row + 4 * u));
    }
#pragma unroll 4
    for (int k = 0; k < HG; k++) {
        float xk = x3[k];
        const float* row = Wfs + (128 + k) * HG + q * 16;
#pragma unroll
        for (int u = 0; u < 4; u++) fma4(acc[u], xk, ld4(row + 4 * u));
    }
#pragma unroll
    for (int u = 0; u < 4; u++) {
        int jb = q * 16 + 4 * u;
        float4 v = acc[u];
        v.x = fmaxf(v.x + fbs[jb], 0.f);
        v.y = fmaxf(v.y + fbs[jb + 1], 0.f);
        v.z = fmaxf(v.z + fbs[jb + 2], 0.f);
        v.w = fmaxf(v.w + fbs[jb + 3], 0.f);
        st4(fs + cl * 68 + jb, v);
    }
    __syncthreads();
    if (t < 64) {
        int c2 = c0 + t;
        float l0 = lbs[0], l1 = lbs[1], l2 = lbs[2], l3 = lbs[3];
        for (int k = 0; k < HG; k++) {
            float fv = fs[t * 68 + k];
            l0 = fmaf(fv, lws[k * 4 + 0], l0);
            l1 = fmaf(fv, lws[k * 4 + 1], l1);
            l2 = fmaf(fv, lws[k * 4 + 2], l2);
            l3 = fmaf(fv, lws[k * 4 + 3], l3);
        }
        float m = fmaxf(fmaxf(l0, l1), fmaxf(l2, l3));
        float e0 = __expf(l0 - m), e1 = __expf(l1 - m), e2 = __expf(l2 - m), e3 = __expf(l3 - m);
        float inv = 1.f / (e0 + e1 + e2 + e3);
        float p0 = e0 * inv, p1 = e1 * inv, p2 = e2 * inv, p3 = e3 * inv;
        float cA = p0, cB = cA + p1, cC = cB + p2, cD = cC + p3;
        const float EPS = 5e-8f, HI = 1.f - 5e-8f;
        float4 r;
        r.x = fminf(fmaxf(cA, EPS), HI);
        r.y = fminf(fmaxf(cB, EPS), HI);
        r.z = fminf(fmaxf(cC, EPS), HI);
        r.w = fminf(fmaxf(cD, EPS), HI);
        st4(out + (size_t)c2 * 4, r);
    }
}

// ---------------- launch ----------------
extern "C" void kernel_launch(void* const* d_in, const int* in_sizes, int n_in,
                              void* d_out, int out_size) {
    const float* daily = (const float*)d_in[0];
    const int* inner = (const int*)d_in[1];
    const int* sector = (const int*)d_in[3];
    const float* gamma = (const float*)d_in[4];
    const float* beta = (const float*)d_in[5];
    const float* Wih = (const float*)d_in[6];
    const float* Whh = (const float*)d_in[7];
    const float* bih = (const float*)d_in[8];
    const float* bhh = (const float*)d_in[9];
    const float* h0 = (const float*)d_in[10];
    const float* W1 = (const float*)d_in[11];
    const float* a1s = (const float*)d_in[12];
    const float* a1d = (const float*)d_in[13];
    const float* b1 = (const float*)d_in[14];
    const float* W2 = (const float*)d_in[15];
    const float* a2s = (const float*)d_in[16];
    const float* a2d = (const float*)d_in[17];
    const float* b2 = (const float*)d_in[18];
    const float* Wf = (const float*)d_in[19];
    const float* fb = (const float*)d_in[20];
    const float* lw = (const float*)d_in[21];
    const float* lb = (const float*)d_in[22];
    float* out = (float*)d_out;
    int E = in_sizes[1] / 2;
    int TOT = E + NCOMP;

    cudaFuncSetAttribute(k_gru, cudaFuncAttributeMaxDynamicSharedMemorySize,
                         SM3_FLOATS * 4);
    cudaFuncSetAttribute(k_fusion, cudaFuncAttributeMaxDynamicSharedMemorySize,
                         SM9_FLOATS * 4);

    k_bn_stats<<<WIN, 256>>>(daily, gamma, beta);
    k_build_wp<<<WIN, G3>>>(Wih, bih);
    k_gru<<<NCOMP / 32, 256, SM3_FLOATS * 4>>>(daily, Whh, bhh, h0);
    k_gat1_node<<<NCOMP / 64, 256>>>(W1, a1s, a1d);
    k_edge_max<<<(TOT + 255) / 256, 256>>>(inner, E);
    k_edge_acc<<<(TOT * 32 + 255) / 256, 256>>>(inner, E);
    k_gat1_fin<<<NCOMP * HG / 256, 256>>>(b1);
    k_pool<<<NSEC, dim3(64, 4)>>>();
    k_gat2<<<1, 256>>>(W2, a2s, a2d, b2);
    k_fusion<<<NCOMP / 64, 256, SM9_FLOATS * 4>>>(sector, Wf, fb, lw, lb, out);
}

// round 3
// speedup vs baseline: 1.0002x; 1.0002x over previous
#include <cuda_runtime.h>
#include <cuda_bf16.h>
#include <cstdint>

#define NCOMP 16384
#define NSEC 64
#define PERSEC 256
#define WIN 32
#define DIN 16
#define HG 64
#define G3 192

// ---------------- scratch (device globals; no allocation) ----------------
__device__ float g_scale[WIN * DIN];
__device__ float g_shift[WIN * DIN];
__device__ float g_Wp[WIN * DIN * G3];
__device__ float g_bp[WIN * G3];
__device__ float g_seq[NCOMP * HG];     // GRU final hidden
__device__ float g_h1[NCOMP * HG];      // GAT1 transformed
__device__ float g_ssrc[NCOMP];
__device__ float g_sdst[NCOMP];
__device__ unsigned g_maxkey[NCOMP];
__device__ float g_denom[NCOMP];
__device__ float g_num[NCOMP * HG];
__device__ float g_intra[NCOMP * HG];
__device__ float g_pool[NSEC * HG];
__device__ float g_sec[NSEC * HG];

// ---------------- helpers ----------------
__device__ __forceinline__ float4 ld4(const float* p) { return *(const float4*)p; }
__device__ __forceinline__ void st4(float* p, float4 v) { *(float4*)p = v; }
__device__ __forceinline__ void fma4(float4& a, float s, float4 b) {
    a.x = fmaf(s, b.x, a.x); a.y = fmaf(s, b.y, a.y);
    a.z = fmaf(s, b.z, a.z); a.w = fmaf(s, b.w, a.w);
}
__device__ __forceinline__ float4 add4(float4 a, float4 b) {
    return make_float4(a.x + b.x, a.y + b.y, a.z + b.z, a.w + b.w);
}
// order-preserving float<->uint for atomicMax on possibly-negative floats
__device__ __forceinline__ unsigned fenc(float f) {
    unsigned u = __float_as_uint(f);
    return (u & 0x80000000u) ? ~u : (u | 0x80000000u);
}
__device__ __forceinline__ float fdec(unsigned k) {
    return (k & 0x80000000u) ? __uint_as_float(k ^ 0x80000000u) : __uint_as_float(~k);
}
__device__ __forceinline__ float lrelu(float v) { return v > 0.f ? v : 0.2f * v; }

// ---------------- K1: BN stats -> scale/shift ----------------
__global__ void k_bn_stats(const float* __restrict__ daily,
                           const float* __restrict__ gamma,
                           const float* __restrict__ beta) {
    int w = blockIdx.x;
    int t = threadIdx.x, lane = t & 31, wid = t >> 5;
    float s[DIN], q[DIN];
#pragma unroll
    for (int d = 0; d < DIN; d++) { s[d] = 0.f; q[d] = 0.f; }
    const float4* base = (const float4*)(daily + (size_t)w * NCOMP * DIN);
    for (int n = t; n < NCOMP; n += 256) {
        float4 vv[4];
        vv[0] = base[n * 4 + 0]; vv[1] = base[n * 4 + 1];
        vv[2] = base[n * 4 + 2]; vv[3] = base[n * 4 + 3];
        const float* v = (const float*)vv;
#pragma unroll
        for (int d = 0; d < DIN; d++) { s[d] += v[d]; q[d] += v[d] * v[d]; }
    }
#pragma unroll
    for (int d = 0; d < DIN; d++) {
        for (int o = 16; o; o >>= 1) {
            s[d] += __shfl_down_sync(0xffffffffu, s[d], o);
            q[d] += __shfl_down_sync(0xffffffffu, q[d], o);
        }
    }
    __shared__ float S[8][DIN], Q[8][DIN];
    if (lane == 0) {
#pragma unroll
        for (int d = 0; d < DIN; d++) { S[wid][d] = s[d]; Q[wid][d] = q[d]; }
    }
    __syncthreads();
    if (t < DIN) {
        float ts = 0.f, tq = 0.f;
#pragma unroll
        for (int r = 0; r < 8; r++) { ts += S[r][t]; tq += Q[r][t]; }
        float mu = ts * (1.f / (float)NCOMP);
        float var = tq * (1.f / (float)NCOMP) - mu * mu;
        int f = w * DIN + t;
        float sc = gamma[f] * rsqrtf(var + 1e-5f);
        g_scale[f] = sc;
        g_shift[f] = beta[f] - mu * sc;
    }
}

// ---------------- K2: folded input-projection weights ----------------
__global__ void k_build_wp(const float* __restrict__ Wih,
                           const float* __restrict__ bih) {
    int w = blockIdx.x;
    int j = threadIdx.x; // 192
    float bp = bih[j];
#pragma unroll
    for (int d = 0; d < DIN; d++) {
        float wij = Wih[d * G3 + j];
        g_Wp[((size_t)w * DIN + d) * G3 + j] = g_scale[w * DIN + d] * wij;
        bp += g_shift[w * DIN + d] * wij;
    }
    g_bp[w * G3 + j] = bp;
}

// ---------------- K3: fused persistent GRU ----------------
// grid 512 blocks x 256 threads; block owns 32 companies; thread = (ci, g):
// ci = company-in-block, g = 8-wide j-slice of the 64 hidden dims.
#define SM3_FLOATS (12288 + 3072 + 192 + 192 + 2 * 32 * 65 + 32 * 17)
__global__ void k_gru(const float* __restrict__ daily,
                      const float* __restrict__ Whh,
                      const float* __restrict__ bhh,
                      const float* __restrict__ h0) {
    extern __shared__ float sm[];
    float* Whh_s = sm;                // 64*192
    float* Wp_s  = sm + 12288;        // 16*192
    float* bp_s  = sm + 15360;        // 192
    float* bhh_s = sm + 15552;        // 192
    float* h_buf = sm + 15744;        // [2][32][65]
    float* x_s   = sm + 15744 + 2 * 32 * 65; // [32][17]
    int t = threadIdx.x;
    int ci = t & 31, g = t >> 5;
    int c0 = blockIdx.x * 32;

    {
        const float4* W4 = (const float4*)Whh;
        float4* Ws4 = (float4*)Whh_s;
        for (int i = t; i < 3072; i += 256) Ws4[i] = W4[i];
        if (t < G3) bhh_s[t] = bhh[t];
        for (int i = t; i < 32 * HG; i += 256) {
            int cc = i >> 6, k = i & 63;
            h_buf[cc * 65 + k] = h0[(size_t)(c0 + cc) * HG + k];
        }
    }
    __syncthreads();

    int cur = 0;
    int j0 = g * 8;
    for (int w = 0; w < WIN; w++) {
        // stage per-step W', b', x
        {
            const float4* Wp4 = (const float4*)(g_Wp + (size_t)w * DIN * G3);
            float4* Wd4 = (float4*)Wp_s;
            for (int i = t; i < 768; i += 256) Wd4[i] = Wp4[i];
            if (t < G3) bp_s[t] = g_bp[w * G3 + t];
            for (int i = t; i < 32 * DIN; i += 256) {
                int cc = i >> 4, d = i & 15;
                x_s[cc * 17 + d] = daily[((size_t)w * NCOMP + c0 + cc) * DIN + d];
            }
        }
        __syncthreads();

        float* h  = h_buf + cur * 2080 + ci * 65;
        float* hn = h_buf + (cur ^ 1) * 2080 + ci * 65;

        float4 aR0 = add4(ld4(bp_s + j0), ld4(bhh_s + j0));
        float4 aR1 = add4(ld4(bp_s + j0 + 4), ld4(bhh_s + j0 + 4));
        float4 aZ0 = add4(ld4(bp_s + 64 + j0), ld4(bhh_s + 64 + j0));
        float4 aZ1 = add4(ld4(bp_s + 64 + j0 + 4), ld4(bhh_s + 64 + j0 + 4));
        float4 aNi0 = ld4(bp_s + 128 + j0);
        float4 aNi1 = ld4(bp_s + 128 + j0 + 4);
        float4 aNh0 = ld4(bhh_s + 128 + j0);
        float4 aNh1 = ld4(bhh_s + 128 + j0 + 4);

#pragma unroll
        for (int d = 0; d < DIN; d++) {
            float xd = x_s[ci * 17 + d];
            const float* row = Wp_s + d * G3 + j0;
            fma4(aR0, xd, ld4(row));        fma4(aR1, xd, ld4(row + 4));
            fma4(aZ0, xd, ld4(row + 64));   fma4(aZ1, xd, ld4(row + 68));
            fma4(aNi0, xd, ld4(row + 128)); fma4(aNi1, xd, ld4(row + 132));
        }
#pragma unroll 8
        for (int k = 0; k < HG; k++) {
            float hk = h[k];
            const float* row = Whh_s + k * G3 + j0;
            fma4(aR0, hk, ld4(row));        fma4(aR1, hk, ld4(row + 4));
            fma4(aZ0, hk, ld4(row + 64));   fma4(aZ1, hk, ld4(row + 68));
            fma4(aNh0, hk, ld4(row + 128)); fma4(aNh1, hk, ld4(row + 132));
        }
        // activations for 8 outputs
        {
            float R[8] = {aR0.x, aR0.y, aR0.z, aR0.w, aR1.x, aR1.y, aR1.z, aR1.w};
            float Z[8] = {aZ0.x, aZ0.y, aZ0.z, aZ0.w, aZ1.x, aZ1.y, aZ1.z, aZ1.w};
            float Ni[8] = {aNi0.x, aNi0.y, aNi0.z, aNi0.w, aNi1.x, aNi1.y, aNi1.z, aNi1.w};
            float Nh[8] = {aNh0.x, aNh0.y, aNh0.z, aNh0.w, aNh1.x, aNh1.y, aNh1.z, aNh1.w};
#pragma unroll
            for (int jj = 0; jj < 8; jj++) {
                float r = 1.f / (1.f + __expf(-R[jj]));
                float z = 1.f / (1.f + __expf(-Z[jj]));
                float n = tanhf(fmaf(r, Nh[jj], Ni[jj]));
                float hold = h[j0 + jj];
                hn[j0 + jj] = fmaf(z, hold - n, n);
            }
        }
        __syncthreads();
        cur ^= 1;
    }
    // writeout
    float* hf = h_buf + cur * 2080;
    for (int i = t; i < 32 * HG; i += 256) {
        int cc = i >> 6, k = i & 63;
        g_seq[(size_t)(c0 + cc) * HG + k] = hf[cc * 65 + k];
    }
}

// ---------------- K4: GAT1 node transform + attention dots + init ----------------
__global__ void k_gat1_node(const float* __restrict__ W1,
                            const float* __restrict__ a1s,
                            const float* __restrict__ a1d) {
    __shared__ float W1s[HG * HG];
    __shared__ float xs[64 * 65];
    __shared__ float as_s[HG], ad_s[HG];
    int t = threadIdx.x;
    int c0 = blockIdx.x * 64;
    for (int i = t; i < HG * HG; i += 256) W1s[i] = W1[i];
    for (int i = t; i < 64 * HG; i += 256) {
        int cc = i >> 6, k = i & 63;
        xs[cc * 65 + k] = g_seq[(size_t)(c0 + cc) * HG + k];
    }
    if (t < HG) { as_s[t] = a1s[t]; ad_s[t] = a1d[t]; }
    __syncthreads();

    int cl = t >> 2, q = t & 3, c = c0 + cl;
    float4 acc[4] = {make_float4(0,0,0,0), make_float4(0,0,0,0),
                     make_float4(0,0,0,0), make_float4(0,0,0,0)};
#pragma unroll 8
    for (int k = 0; k < HG; k++) {
        float x = xs[cl * 65 + k];
        const float* row = W1s + k * HG + q * 16;
#pragma unroll
        for (int u = 0; u < 4; u++) fma4(acc[u], x, ld4(row + 4 * u));
    }
    float ps = 0.f, pd = 0.f;
#pragma unroll
    for (int u = 0; u < 4; u++) {
        int jb = q * 16 + 4 * u;
        const float* a = (const float*)&acc[u];
#pragma unroll
        for (int e = 0; e < 4; e++) {
            ps += a[e] * as_s[jb + e];
            pd += a[e] * ad_s[jb + e];
        }
        st4(g_h1 + (size_t)c * HG + jb, acc[u]);
        st4(g_num + (size_t)c * HG + jb, make_float4(0, 0, 0, 0));
    }
    ps += __shfl_xor_sync(0xffffffffu, ps, 1);
    ps += __shfl_xor_sync(0xffffffffu, ps, 2);
    pd += __shfl_xor_sync(0xffffffffu, pd, 1);
    pd += __shfl_xor_sync(0xffffffffu, pd, 2);
    if (q == 0) {
        g_ssrc[c] = ps; g_sdst[c] = pd;
        g_maxkey[c] = 0u; g_denom[c] = 0.f;
    }
}

// ---------------- K5: edge softmax max pass ----------------
__global__ void k_edge_max(const int* __restrict__ edges, int E) {
    int idx = blockIdx.x * 256 + threadIdx.x;
    int TOT = E + NCOMP;
    if (idx >= TOT) return;
    int src, dst;
    if (idx < E) { src = edges[idx]; dst = edges[E + idx]; }
    else { src = dst = idx - E; }
    float e = lrelu(g_ssrc[src] + g_sdst[dst]);
    atomicMax(&g_maxkey[dst], fenc(e));
}

// ---------------- K6: edge accumulate pass (warp per edge) ----------------
__global__ void k_edge_acc(const int* __restrict__ edges, int E) {
    int gt = blockIdx.x * 256 + threadIdx.x;
    int gw = gt >> 5, lane = gt & 31;
    int TOT = E + NCOMP;
    if (gw >= TOT) return;
    int src, dst;
    if (gw < E) { src = edges[gw]; dst = edges[E + gw]; }
    else { src = dst = gw - E; }
    float e = lrelu(g_ssrc[src] + g_sdst[dst]);
    float m = fdec(g_maxkey[dst]);
    float wexp = __expf(e - m);
    if (lane == 0) atomicAdd(&g_denom[dst], wexp);
    const float* hs = g_h1 + (size_t)src * HG;
    float* np = g_num + (size_t)dst * HG;
    atomicAdd(np + lane, wexp * hs[lane]);
    atomicAdd(np + lane + 32, wexp * hs[lane + 32]);
}

// ---------------- K7: finalize GAT1 ----------------
__global__ void k_gat1_fin(const float* __restrict__ b1) {
    int idx = blockIdx.x * 256 + threadIdx.x;
    int c = idx >> 6, j = idx & 63;
    g_intra[idx] = g_num[idx] / (g_denom[c] + 1e-16f) + b1[j];
}

// ---------------- K7b: sector max pool ----------------
__global__ void k_pool() {
    int s = blockIdx.x;
    int tx = threadIdx.x, ty = threadIdx.y;
    float m = -3.4e38f;
    for (int cc = ty; cc < PERSEC; cc += 4)
        m = fmaxf(m, g_intra[((size_t)(s * PERSEC + cc)) * HG + tx]);
    __shared__ float red[4][64];
    red[ty][tx] = m;
    __syncthreads();
    if (ty == 0) {
        m = fmaxf(fmaxf(red[0][tx], red[1][tx]), fmaxf(red[2][tx], red[3][tx]));
        g_pool[s * HG + tx] = m;
    }
}

// ---------------- K8: GAT2 on 64 sectors (dense) — single block ----------------
__global__ void k_gat2(const float* __restrict__ W2,
                       const float* __restrict__ a2s,
                       const float* __restrict__ a2d,
                       const float* __restrict__ b2) {
    __shared__ float W2s[HG * HG];      // reused as alpha after phase B
    __shared__ float h2s[64 * 68];
    __shared__ float ss[64], sd[64], as_s[64], ad_s[64];
    int t = threadIdx.x;
    for (int i = t; i < HG * HG; i += 256) W2s[i] = W2[i];
    if (t < 64) { as_s[t] = a2s[t]; ad_s[t] = a2d[t]; }
    __syncthreads();

    int i = t >> 2, q = t & 3;
    {
        float4 acc[4] = {make_float4(0,0,0,0), make_float4(0,0,0,0),
                         make_float4(0,0,0,0), make_float4(0,0,0,0)};
        for (int k = 0; k < HG; k++) {
            float x = g_pool[i * HG + k];
            const float* row = W2s + k * HG + q * 16;
#pragma unroll
            for (int u = 0; u < 4; u++) fma4(acc[u], x, ld4(row + 4 * u));
        }
#pragma unroll
        for (int u = 0; u < 4; u++) st4(h2s + i * 68 + q * 16 + 4 * u, acc[u]);
    }
    __syncthreads();
    if (t < 64) {
        float s1 = 0.f, s2 = 0.f;
        for (int k = 0; k < HG; k++) {
            float v = h2s[t * 68 + k];
            s1 += v * as_s[k]; s2 += v * ad_s[k];
        }
        ss[t] = s1; sd[t] = s2;
    }
    __syncthreads();
    // alpha (overwrite W2s)
    {
        int wi = t >> 5, lane = t & 31;
        for (int dst = wi; dst < 64; dst += 8) {
            float e1 = lrelu(ss[lane] + sd[dst]);
            float e2 = lrelu(ss[lane + 32] + sd[dst]);
            float m = fmaxf(e1, e2);
            for (int o = 16; o; o >>= 1) m = fmaxf(m, __shfl_xor_sync(0xffffffffu, m, o));
            float w1 = __expf(e1 - m), w2 = __expf(e2 - m);
            float s = w1 + w2;
            for (int o = 16; o; o >>= 1) s += __shfl_xor_sync(0xffffffffu, s, o);
            float inv = 1.f / (s + 1e-16f);
            W2s[dst * 64 + lane] = w1 * inv;
            W2s[dst * 64 + lane + 32] = w2 * inv;
        }
    }
    __syncthreads();
    {
        int dst = i;
        float4 o[4] = {make_float4(0,0,0,0), make_float4(0,0,0,0),
                       make_float4(0,0,0,0), make_float4(0,0,0,0)};
        for (int src = 0; src < 64; src++) {
            float a = W2s[dst * 64 + src];
            const float* row = h2s + src * 68 + q * 16;
#pragma unroll
            for (int u = 0; u < 4; u++) fma4(o[u], a, ld4(row + 4 * u));
        }
#pragma unroll
        for (int u = 0; u < 4; u++) {
            int jb = q * 16 + 4 * u;
            float4 v = o[u];
            v.x += b2[jb]; v.y += b2[jb + 1]; v.z += b2[jb + 2]; v.w += b2[jb + 3];
            st4(g_sec + dst * HG + jb, v);
        }
    }
}

// ---------------- K9: fusion + logits + softmax/cumsum/clip ----------------
#define SM9_FLOATS (12288 + 64 * 68 + 256 + 4 + 64)
__global__ void k_fusion(const int* __restrict__ sector_ids,
                         const float* __restrict__ Wf,
                         const float* __restrict__ fb,
                         const float* __restrict__ lw,
                         const float* __restrict__ lb,
                         float* __restrict__ out) {
    extern __shared__ float sm[];
    float* Wfs = sm;                 // 192*64
    float* fs  = sm + 12288;         // 64*68
    float* lws = sm + 12288 + 64 * 68;   // 64*4
    float* lbs = lws + 256;          // 4
    float* fbs = lbs + 4;            // 64
    int t = threadIdx.x;
    int c0 = blockIdx.x * 64;
    {
        const float4* w4 = (const float4*)Wf;
        float4* d4 = (float4*)Wfs;
        for (int i = t; i < 3072; i += 256) d4[i] = w4[i];
        if (t < 256) lws[t] = lw[t];
        if (t < 4) lbs[t] = lb[t];
        if (t < 64) fbs[t] = fb[t];
    }
    __syncthreads();

    int cl = t >> 2, q = t & 3, c = c0 + cl;
    int sec = sector_ids[c];
    const float* x1 = g_seq + (size_t)c * HG;
    const float* x2 = g_sec + (size_t)sec * HG;
    const float* x3 = g_intra + (size_t)c * HG;
    float4 acc[4] = {make_float4(0,0,0,0), make_float4(0,0,0,0),
                     make_float4(0,0,0,0), make_float4(0,0,0,0)};
#pragma unroll 4
    for (int k = 0; k < HG; k++) {
        float xk = x1[k];
        const float* row = Wfs + k * HG + q * 16;
#pragma unroll
        for (int u = 0; u < 4; u++) fma4(acc[u], xk, ld4(row + 4 * u));
    }
#pragma unroll 4
    for (int k = 0; k < HG; k++) {
        float xk = x2[k];
        const float* row = Wfs + (64 + k) * HG + q * 16;
#pragma unroll
        for (int u = 0; u < 4; u++) fma4(acc[u], xk, ld4(row + 4 * u));
    }
#pragma unroll 4
    for (int k = 0; k < HG; k++) {
        float xk = x3[k];
        const float* row = Wfs + (128 + k) * HG + q * 16;
#pragma unroll
        for (int u = 0; u < 4; u++) fma4(acc[u], xk, ld4(row + 4 * u));
    }
#pragma unroll
    for (int u = 0; u < 4; u++) {
        int jb = q * 16 + 4 * u;
        float4 v = acc[u];
        v.x = fmaxf(v.x + fbs[jb], 0.f);
        v.y = fmaxf(v.y + fbs[jb + 1], 0.f);
        v.z = fmaxf(v.z + fbs[jb + 2], 0.f);
        v.w = fmaxf(v.w + fbs[jb + 3], 0.f);
        st4(fs + cl * 68 + jb, v);
    }
    __syncthreads();
    if (t < 64) {
        int c2 = c0 + t;
        float l0 = lbs[0], l1 = lbs[1], l2 = lbs[2], l3 = lbs[3];
        for (int k = 0; k < HG; k++) {
            float fv = fs[t * 68 + k];
            l0 = fmaf(fv, lws[k * 4 + 0], l0);
            l1 = fmaf(fv, lws[k * 4 + 1], l1);
            l2 = fmaf(fv, lws[k * 4 + 2], l2);
            l3 = fmaf(fv, lws[k * 4 + 3], l3);
        }
        float m = fmaxf(fmaxf(l0, l1), fmaxf(l2, l3));
        float e0 = __expf(l0 - m), e1 = __expf(l1 - m), e2 = __expf(l2 - m), e3 = __expf(l3 - m);
        float inv = 1.f / (e0 + e1 + e2 + e3);
        float p0 = e0 * inv, p1 = e1 * inv, p2 = e2 * inv, p3 = e3 * inv;
        float cA = p0, cB = cA + p1, cC = cB + p2, cD = cC + p3;
        const float EPS = 5e-8f, HI = 1.f - 5e-8f;
        float4 r;
        r.x = fminf(fmaxf(cA, EPS), HI);
        r.y = fminf(fmaxf(cB, EPS), HI);
        r.z = fminf(fmaxf(cC, EPS), HI);
        r.w = fminf(fmaxf(cD, EPS), HI);
        st4(out + (size_t)c2 * 4, r);
    }
}

// ---------------- launch ----------------
extern "C" void kernel_launch(void* const* d_in, const int* in_sizes, int n_in,
                              void* d_out, int out_size) {
    const float* daily = (const float*)d_in[0];
    const int* inner = (const int*)d_in[1];
    const int* sector = (const int*)d_in[3];
    const float* gamma = (const float*)d_in[4];
    const float* beta = (const float*)d_in[5];
    const float* Wih = (const float*)d_in[6];
    const float* Whh = (const float*)d_in[7];
    const float* bih = (const float*)d_in[8];
    const float* bhh = (const float*)d_in[9];
    const float* h0 = (const float*)d_in[10];
    const float* W1 = (const float*)d_in[11];
    const float* a1s = (const float*)d_in[12];
    const float* a1d = (const float*)d_in[13];
    const float* b1 = (const float*)d_in[14];
    const float* W2 = (const float*)d_in[15];
    const float* a2s = (const float*)d_in[16];
    const float* a2d = (const float*)d_in[17];
    const float* b2 = (const float*)d_in[18];
    const float* Wf = (const float*)d_in[19];
    const float* fb = (const float*)d_in[20];
    const float* lw = (const float*)d_in[21];
    const float* lb = (const float*)d_in[22];
    float* out = (float*)d_out;
    int E = in_sizes[1] / 2;
    int TOT = E + NCOMP;

    cudaFuncSetAttribute(k_gru, cudaFuncAttributeMaxDynamicSharedMemorySize,
                         SM3_FLOATS * 4);
    cudaFuncSetAttribute(k_fusion, cudaFuncAttributeMaxDynamicSharedMemorySize,
                         SM9_FLOATS * 4);

    k_bn_stats<<<WIN, 256>>>(daily, gamma, beta);
    k_build_wp<<<WIN, G3>>>(Wih, bih);
    k_gru<<<NCOMP / 32, 256, SM3_FLOATS * 4>>>(daily, Whh, bhh, h0);
    k_gat1_node<<<NCOMP / 64, 256>>>(W1, a1s, a1d);
    k_edge_max<<<(TOT + 255) / 256, 256>>>(inner, E);
    k_edge_acc<<<(TOT * 32 + 255) / 256, 256>>>(inner, E);
    k_gat1_fin<<<NCOMP * HG / 256, 256>>>(b1);
    k_pool<<<NSEC, dim3(64, 4)>>>();
    k_gat2<<<1, 256>>>(W2, a2s, a2d, b2);
    k_fusion<<<NCOMP / 64, 256, SM9_FLOATS * 4>>>(sector, Wf, fb, lw, lb, out);
}

// round 4
// speedup vs baseline: 1.1178x; 1.1176x over previous
#include <cuda_runtime.h>
#include <cuda_bf16.h>
#include <cstdint>

#define NCOMP 16384
#define NSEC 64
#define PERSEC 256
#define WIN 32
#define DIN 16
#define HG 64
#define G3 192
#define EMAX 524288

typedef unsigned long long u64;

// ---------------- scratch (device globals; no allocation) ----------------
__device__ float g_scale[WIN * DIN];
__device__ float g_shift[WIN * DIN];
__device__ float g_Wp[WIN * DIN * G3];
__device__ float g_bp[WIN * G3];
__device__ float g_seq[NCOMP * HG];
__device__ float g_h1[NCOMP * HG];
__device__ float g_ssrc[NCOMP];
__device__ float g_sdst[NCOMP];
__device__ float g_intra[NCOMP * HG];
__device__ float g_pool[NSEC * HG];
__device__ float g_sec[NSEC * HG];
__device__ int g_deg[NCOMP];
__device__ int g_off[NCOMP + 1];
__device__ int g_cursor[NCOMP];
__device__ int g_blksum[64];
__device__ int g_csr[EMAX];

// ---------------- helpers ----------------
__device__ __forceinline__ float4 ld4(const float* p) { return *(const float4*)p; }
__device__ __forceinline__ void st4(float* p, float4 v) { *(float4*)p = v; }
__device__ __forceinline__ void fma4(float4& a, float s, float4 b) {
    a.x = fmaf(s, b.x, a.x); a.y = fmaf(s, b.y, a.y);
    a.z = fmaf(s, b.z, a.z); a.w = fmaf(s, b.w, a.w);
}
__device__ __forceinline__ float lrelu(float v) { return v > 0.f ? v : 0.2f * v; }

// f32x2 packed ops (sm_103a FFMA2 path — only reachable via PTX)
__device__ __forceinline__ u64 pk2(float x) {
    u64 r; asm("mov.b64 %0, {%1, %1};" : "=l"(r) : "f"(x)); return r;
}
__device__ __forceinline__ void up2(u64 v, float& x, float& y) {
    asm("mov.b64 {%0, %1}, %2;" : "=f"(x), "=f"(y) : "l"(v));
}
__device__ __forceinline__ void ffma2(u64& d, u64 a, u64 b) {
    asm("fma.rn.f32x2 %0, %1, %2, %0;" : "+l"(d) : "l"(a), "l"(b));
}
__device__ __forceinline__ u64 fadd2(u64 a, u64 b) {
    u64 r; asm("add.rn.f32x2 %0, %1, %2;" : "=l"(r) : "l"(a), "l"(b)); return r;
}

// ---------------- K1: BN stats -> scale/shift ----------------
__global__ void k_bn_stats(const float* __restrict__ daily,
                           const float* __restrict__ gamma,
                           const float* __restrict__ beta) {
    int w = blockIdx.x;
    int t = threadIdx.x, lane = t & 31, wid = t >> 5;
    float s[DIN], q[DIN];
#pragma unroll
    for (int d = 0; d < DIN; d++) { s[d] = 0.f; q[d] = 0.f; }
    const float4* base = (const float4*)(daily + (size_t)w * NCOMP * DIN);
    for (int n = t; n < NCOMP; n += 256) {
        float4 vv[4];
        vv[0] = base[n * 4 + 0]; vv[1] = base[n * 4 + 1];
        vv[2] = base[n * 4 + 2]; vv[3] = base[n * 4 + 3];
        const float* v = (const float*)vv;
#pragma unroll
        for (int d = 0; d < DIN; d++) { s[d] += v[d]; q[d] += v[d] * v[d]; }
    }
#pragma unroll
    for (int d = 0; d < DIN; d++) {
        for (int o = 16; o; o >>= 1) {
            s[d] += __shfl_down_sync(0xffffffffu, s[d], o);
            q[d] += __shfl_down_sync(0xffffffffu, q[d], o);
        }
    }
    __shared__ float S[8][DIN], Q[8][DIN];
    if (lane == 0) {
#pragma unroll
        for (int d = 0; d < DIN; d++) { S[wid][d] = s[d]; Q[wid][d] = q[d]; }
    }
    __syncthreads();
    if (t < DIN) {
        float ts = 0.f, tq = 0.f;
#pragma unroll
        for (int r = 0; r < 8; r++) { ts += S[r][t]; tq += Q[r][t]; }
        float mu = ts * (1.f / (float)NCOMP);
        float var = tq * (1.f / (float)NCOMP) - mu * mu;
        int f = w * DIN + t;
        float sc = gamma[f] * rsqrtf(var + 1e-5f);
        g_scale[f] = sc;
        g_shift[f] = beta[f] - mu * sc;
    }
}

// ---------------- K2: folded input-projection weights ----------------
__global__ void k_build_wp(const float* __restrict__ Wih,
                           const float* __restrict__ bih) {
    int w = blockIdx.x;
    int j = threadIdx.x;
    float bp = bih[j];
#pragma unroll
    for (int d = 0; d < DIN; d++) {
        float wij = Wih[d * G3 + j];
        g_Wp[((size_t)w * DIN + d) * G3 + j] = g_scale[w * DIN + d] * wij;
        bp += g_shift[w * DIN + d] * wij;
    }
    g_bp[w * G3 + j] = bp;
}

// ---------------- K3: fused persistent GRU with FFMA2 ----------------
#define SM3_FLOATS (12288 + 3072 + 192 + 192 + 2 * 32 * 65 + 32 * 17)
__global__ void k_gru(const float* __restrict__ daily,
                      const float* __restrict__ Whh,
                      const float* __restrict__ bhh,
                      const float* __restrict__ h0) {
    extern __shared__ float sm[];
    float* Whh_s = sm;                 // 64*192
    float* Wp_s  = sm + 12288;         // 16*192
    float* bp_s  = sm + 15360;         // 192
    float* bhh_s = sm + 15552;         // 192
    float* h_buf = sm + 15744;         // [2][32][65]
    float* x_s   = sm + 15744 + 2 * 32 * 65; // [32][17]
    int t = threadIdx.x;
    int ci = t & 31, g = t >> 5;
    int c0 = blockIdx.x * 32;

    {
        const float4* W4 = (const float4*)Whh;
        float4* Ws4 = (float4*)Whh_s;
        for (int i = t; i < 3072; i += 256) Ws4[i] = W4[i];
        if (t < G3) bhh_s[t] = bhh[t];
        for (int i = t; i < 32 * HG; i += 256) {
            int cc = i >> 6, k = i & 63;
            h_buf[cc * 65 + k] = h0[(size_t)(c0 + cc) * HG + k];
        }
    }
    __syncthreads();

    int cur = 0;
    int j0 = g * 8;
    for (int w = 0; w < WIN; w++) {
        {
            const float4* Wp4 = (const float4*)(g_Wp + (size_t)w * DIN * G3);
            float4* Wd4 = (float4*)Wp_s;
            for (int i = t; i < 768; i += 256) Wd4[i] = Wp4[i];
            if (t < G3) bp_s[t] = g_bp[w * G3 + t];
            for (int i = t; i < 32 * DIN; i += 256) {
                int cc = i >> 4, d = i & 15;
                x_s[cc * 17 + d] = daily[((size_t)w * NCOMP + c0 + cc) * DIN + d];
            }
        }
        __syncthreads();

        float* h  = h_buf + cur * 2080 + ci * 65;
        float* hn = h_buf + (cur ^ 1) * 2080 + ci * 65;

        u64 aR[4], aZ[4], aNi[4], aNh[4];
        {
            ulonglong2 b0 = *(const ulonglong2*)(bp_s + j0);
            ulonglong2 b1 = *(const ulonglong2*)(bp_s + j0 + 4);
            ulonglong2 c0v = *(const ulonglong2*)(bhh_s + j0);
            ulonglong2 c1v = *(const ulonglong2*)(bhh_s + j0 + 4);
            aR[0] = fadd2(b0.x, c0v.x); aR[1] = fadd2(b0.y, c0v.y);
            aR[2] = fadd2(b1.x, c1v.x); aR[3] = fadd2(b1.y, c1v.y);
            ulonglong2 z0 = *(const ulonglong2*)(bp_s + 64 + j0);
            ulonglong2 z1 = *(const ulonglong2*)(bp_s + 64 + j0 + 4);
            ulonglong2 y0 = *(const ulonglong2*)(bhh_s + 64 + j0);
            ulonglong2 y1 = *(const ulonglong2*)(bhh_s + 64 + j0 + 4);
            aZ[0] = fadd2(z0.x, y0.x); aZ[1] = fadd2(z0.y, y0.y);
            aZ[2] = fadd2(z1.x, y1.x); aZ[3] = fadd2(z1.y, y1.y);
            ulonglong2 n0 = *(const ulonglong2*)(bp_s + 128 + j0);
            ulonglong2 n1 = *(const ulonglong2*)(bp_s + 128 + j0 + 4);
            aNi[0] = n0.x; aNi[1] = n0.y; aNi[2] = n1.x; aNi[3] = n1.y;
            ulonglong2 m0 = *(const ulonglong2*)(bhh_s + 128 + j0);
            ulonglong2 m1 = *(const ulonglong2*)(bhh_s + 128 + j0 + 4);
            aNh[0] = m0.x; aNh[1] = m0.y; aNh[2] = m1.x; aNh[3] = m1.y;
        }

#pragma unroll
        for (int d = 0; d < DIN; d++) {
            u64 xd = pk2(x_s[ci * 17 + d]);
            const float* row = Wp_s + d * G3 + j0;
            ulonglong2 r0 = *(const ulonglong2*)(row);
            ulonglong2 r1 = *(const ulonglong2*)(row + 4);
            ulonglong2 z0 = *(const ulonglong2*)(row + 64);
            ulonglong2 z1 = *(const ulonglong2*)(row + 68);
            ulonglong2 n0 = *(const ulonglong2*)(row + 128);
            ulonglong2 n1 = *(const ulonglong2*)(row + 132);
            ffma2(aR[0], xd, r0.x); ffma2(aR[1], xd, r0.y);
            ffma2(aR[2], xd, r1.x); ffma2(aR[3], xd, r1.y);
            ffma2(aZ[0], xd, z0.x); ffma2(aZ[1], xd, z0.y);
            ffma2(aZ[2], xd, z1.x); ffma2(aZ[3], xd, z1.y);
            ffma2(aNi[0], xd, n0.x); ffma2(aNi[1], xd, n0.y);
            ffma2(aNi[2], xd, n1.x); ffma2(aNi[3], xd, n1.y);
        }
#pragma unroll 4
        for (int k = 0; k < HG; k++) {
            u64 hk = pk2(h[k]);
            const float* row = Whh_s + k * G3 + j0;
            ulonglong2 r0 = *(const ulonglong2*)(row);
            ulonglong2 r1 = *(const ulonglong2*)(row + 4);
            ulonglong2 z0 = *(const ulonglong2*)(row + 64);
            ulonglong2 z1 = *(const ulonglong2*)(row + 68);
            ulonglong2 n0 = *(const ulonglong2*)(row + 128);
            ulonglong2 n1 = *(const ulonglong2*)(row + 132);
            ffma2(aR[0], hk, r0.x); ffma2(aR[1], hk, r0.y);
            ffma2(aR[2], hk, r1.x); ffma2(aR[3], hk, r1.y);
            ffma2(aZ[0], hk, z0.x); ffma2(aZ[1], hk, z0.y);
            ffma2(aZ[2], hk, z1.x); ffma2(aZ[3], hk, z1.y);
            ffma2(aNh[0], hk, n0.x); ffma2(aNh[1], hk, n0.y);
            ffma2(aNh[2], hk, n1.x); ffma2(aNh[3], hk, n1.y);
        }
        {
            float R8[8], Z8[8], NI8[8], NH8[8];
#pragma unroll
            for (int q = 0; q < 4; q++) {
                up2(aR[q], R8[2 * q], R8[2 * q + 1]);
                up2(aZ[q], Z8[2 * q], Z8[2 * q + 1]);
                up2(aNi[q], NI8[2 * q], NI8[2 * q + 1]);
                up2(aNh[q], NH8[2 * q], NH8[2 * q + 1]);
            }
#pragma unroll
            for (int jj = 0; jj < 8; jj++) {
                float r = __fdividef(1.f, 1.f + __expf(-R8[jj]));
                float z = __fdividef(1.f, 1.f + __expf(-Z8[jj]));
                float pre = fmaf(r, NH8[jj], NI8[jj]);
                float n = __fdividef(2.f, 1.f + __expf(-2.f * pre)) - 1.f;
                float hold = h[j0 + jj];
                hn[j0 + jj] = fmaf(z, hold - n, n);
            }
        }
        __syncthreads();
        cur ^= 1;
    }
    float* hf = h_buf + cur * 2080;
    for (int i = t; i < 32 * HG; i += 256) {
        int cc = i >> 6, k = i & 63;
        g_seq[(size_t)(c0 + cc) * HG + k] = hf[cc * 65 + k];
    }
}

// ---------------- K4: GAT1 node transform + attention dots ----------------
__global__ void k_gat1_node(const float* __restrict__ W1,
                            const float* __restrict__ a1s,
                            const float* __restrict__ a1d) {
    __shared__ float W1s[HG * HG];
    __shared__ float xs[64 * 65];
    __shared__ float as_s[HG], ad_s[HG];
    int t = threadIdx.x;
    int c0 = blockIdx.x * 64;
    for (int i = t; i < HG * HG; i += 256) W1s[i] = W1[i];
    for (int i = t; i < 64 * HG; i += 256) {
        int cc = i >> 6, k = i & 63;
        xs[cc * 65 + k] = g_seq[(size_t)(c0 + cc) * HG + k];
    }
    if (t < HG) { as_s[t] = a1s[t]; ad_s[t] = a1d[t]; }
    __syncthreads();

    int cl = t >> 2, q = t & 3, c = c0 + cl;
    float4 acc[4] = {make_float4(0,0,0,0), make_float4(0,0,0,0),
                     make_float4(0,0,0,0), make_float4(0,0,0,0)};
#pragma unroll 8
    for (int k = 0; k < HG; k++) {
        float x = xs[cl * 65 + k];
        const float* row = W1s + k * HG + q * 16;
#pragma unroll
        for (int u = 0; u < 4; u++) fma4(acc[u], x, ld4(row + 4 * u));
    }
    float ps = 0.f, pd = 0.f;
#pragma unroll
    for (int u = 0; u < 4; u++) {
        int jb = q * 16 + 4 * u;
        const float* a = (const float*)&acc[u];
#pragma unroll
        for (int e = 0; e < 4; e++) {
            ps += a[e] * as_s[jb + e];
            pd += a[e] * ad_s[jb + e];
        }
        st4(g_h1 + (size_t)c * HG + jb, acc[u]);
    }
    ps += __shfl_xor_sync(0xffffffffu, ps, 1);
    ps += __shfl_xor_sync(0xffffffffu, ps, 2);
    pd += __shfl_xor_sync(0xffffffffu, pd, 1);
    pd += __shfl_xor_sync(0xffffffffu, pd, 2);
    if (q == 0) { g_ssrc[c] = ps; g_sdst[c] = pd; }
}

// ---------------- CSR build ----------------
__global__ void k_deg0() { g_deg[blockIdx.x * 256 + threadIdx.x] = 0; }
__global__ void k_deg(const int* __restrict__ e, int E) {
    int i = blockIdx.x * 256 + threadIdx.x;
    if (i < E) atomicAdd(&g_deg[e[E + i]], 1);
}
__global__ void k_scan1() {
    __shared__ int s[256];
    int b = blockIdx.x, t = threadIdx.x, i = b * 256 + t;
    int d = g_deg[i];
    s[t] = d;
    __syncthreads();
    for (int o = 1; o < 256; o <<= 1) {
        int v = (t >= o) ? s[t - o] : 0;
        __syncthreads();
        s[t] += v;
        __syncthreads();
    }
    g_off[i] = s[t] - d;
    if (t == 255) g_blksum[b] = s[255];
}
__global__ void k_scan2(int E) {
    if (threadIdx.x == 0) {
        int a = 0;
        for (int b = 0; b < 64; b++) { int v = g_blksum[b]; g_blksum[b] = a; a += v; }
        g_off[NCOMP] = E;
    }
}
__global__ void k_scan3() {
    int b = blockIdx.x, i = b * 256 + threadIdx.x;
    int o = g_off[i] + g_blksum[b];
    g_off[i] = o;
    g_cursor[i] = o;
}
__global__ void k_scatter(const int* __restrict__ e, int E) {
    int i = blockIdx.x * 256 + threadIdx.x;
    if (i < E) {
        int d = e[E + i];
        int p = atomicAdd(&g_cursor[d], 1);
        if (p < EMAX) g_csr[p] = e[i];
    }
}

// ---------------- K6: warp-per-dst online softmax aggregate ----------------
__global__ void k_agg(const float* __restrict__ b1) {
    int gw = (blockIdx.x * 256 + threadIdx.x) >> 5;
    int lane = threadIdx.x & 31;
    int dst = gw;
    float sd = g_sdst[dst];
    float m = lrelu(g_ssrc[dst] + sd);      // self-loop score
    float den = 1.f;                        // exp(self - m) = 1
    float a0 = g_h1[(size_t)dst * HG + lane];
    float a1 = g_h1[(size_t)dst * HG + lane + 32];
    int s = g_off[dst], e = g_off[dst + 1];
    for (int base = s; base < e; base += 32) {
        int p = base + lane;
        bool valid = p < e;
        int src = valid ? g_csr[p] : 0;
        float ev = valid ? lrelu(g_ssrc[src] + sd) : -3.4e38f;
        float cm = ev;
        for (int o = 16; o; o >>= 1)
            cm = fmaxf(cm, __shfl_xor_sync(0xffffffffu, cm, o));
        if (cm > m) {
            float f = __expf(m - cm);
            a0 *= f; a1 *= f; den *= f;
            m = cm;
        }
        int cnt = min(32, e - base);
        for (int j = 0; j < cnt; j++) {
            int sj = __shfl_sync(0xffffffffu, src, j);
            float ej = __shfl_sync(0xffffffffu, ev, j);
            float wj = __expf(ej - m);
            den += wj;
            a0 = fmaf(wj, g_h1[(size_t)sj * HG + lane], a0);
            a1 = fmaf(wj, g_h1[(size_t)sj * HG + lane + 32], a1);
        }
    }
    float inv = __fdividef(1.f, den + 1e-16f);
    g_intra[(size_t)dst * HG + lane] = a0 * inv + b1[lane];
    g_intra[(size_t)dst * HG + lane + 32] = a1 * inv + b1[lane + 32];
}

// ---------------- K7b: sector max pool ----------------
__global__ void k_pool() {
    int s = blockIdx.x;
    int tx = threadIdx.x, ty = threadIdx.y;
    float m = -3.4e38f;
    for (int cc = ty; cc < PERSEC; cc += 4)
        m = fmaxf(m, g_intra[((size_t)(s * PERSEC + cc)) * HG + tx]);
    __shared__ float red[4][64];
    red[ty][tx] = m;
    __syncthreads();
    if (ty == 0) {
        m = fmaxf(fmaxf(red[0][tx], red[1][tx]), fmaxf(red[2][tx], red[3][tx]));
        g_pool[s * HG + tx] = m;
    }
}

// ---------------- K8: GAT2 on 64 sectors (dense, one block) ----------------
__global__ void k_gat2(const float* __restrict__ W2,
                       const float* __restrict__ a2s,
                       const float* __restrict__ a2d,
                       const float* __restrict__ b2) {
    __shared__ float W2s[HG * HG];
    __shared__ float h2s[64 * 68];
    __shared__ float ss[64], sd[64], as_s[64], ad_s[64];
    int t = threadIdx.x;
    for (int i = t; i < HG * HG; i += 256) W2s[i] = W2[i];
    if (t < 64) { as_s[t] = a2s[t]; ad_s[t] = a2d[t]; }
    __syncthreads();

    int i = t >> 2, q = t & 3;
    {
        float4 acc[4] = {make_float4(0,0,0,0), make_float4(0,0,0,0),
                         make_float4(0,0,0,0), make_float4(0,0,0,0)};
        for (int k = 0; k < HG; k++) {
            float x = g_pool[i * HG + k];
            const float* row = W2s + k * HG + q * 16;
#pragma unroll
            for (int u = 0; u < 4; u++) fma4(acc[u], x, ld4(row + 4 * u));
        }
#pragma unroll
        for (int u = 0; u < 4; u++) st4(h2s + i * 68 + q * 16 + 4 * u, acc[u]);
    }
    __syncthreads();
    if (t < 64) {
        float s1 = 0.f, s2 = 0.f;
        for (int k = 0; k < HG; k++) {
            float v = h2s[t * 68 + k];
            s1 += v * as_s[k]; s2 += v * ad_s[k];
        }
        ss[t] = s1; sd[t] = s2;
    }
    __syncthreads();
    {
        int wi = t >> 5, lane = t & 31;
        for (int dst = wi; dst < 64; dst += 8) {
            float e1 = lrelu(ss[lane] + sd[dst]);
            float e2 = lrelu(ss[lane + 32] + sd[dst]);
            float m = fmaxf(e1, e2);
            for (int o = 16; o; o >>= 1) m = fmaxf(m, __shfl_xor_sync(0xffffffffu, m, o));
            float w1 = __expf(e1 - m), w2 = __expf(e2 - m);
            float s = w1 + w2;
            for (int o = 16; o; o >>= 1) s += __shfl_xor_sync(0xffffffffu, s, o);
            float inv = 1.f / (s + 1e-16f);
            W2s[dst * 64 + lane] = w1 * inv;
            W2s[dst * 64 + lane + 32] = w2 * inv;
        }
    }
    __syncthreads();
    {
        int dst = i;
        float4 o[4] = {make_float4(0,0,0,0), make_float4(0,0,0,0),
                       make_float4(0,0,0,0), make_float4(0,0,0,0)};
        for (int src = 0; src < 64; src++) {
            float a = W2s[dst * 64 + src];
            const float* row = h2s + src * 68 + q * 16;
#pragma unroll
            for (int u = 0; u < 4; u++) fma4(o[u], a, ld4(row + 4 * u));
        }
#pragma unroll
        for (int u = 0; u < 4; u++) {
            int jb = q * 16 + 4 * u;
            float4 v = o[u];
            v.x += b2[jb]; v.y += b2[jb + 1]; v.z += b2[jb + 2]; v.w += b2[jb + 3];
            st4(g_sec + dst * HG + jb, v);
        }
    }
}

// ---------------- K9: fusion + logits + softmax/cumsum/clip ----------------
#define SM9_FLOATS (12288 + 64 * 68 + 256 + 4 + 64)
__global__ void k_fusion(const int* __restrict__ sector_ids,
                         const float* __restrict__ Wf,
                         const float* __restrict__ fb,
                         const float* __restrict__ lw,
                         const float* __restrict__ lb,
                         float* __restrict__ out) {
    extern __shared__ float sm[];
    float* Wfs = sm;
    float* fs  = sm + 12288;
    float* lws = sm + 12288 + 64 * 68;
    float* lbs = lws + 256;
    float* fbs = lbs + 4;
    int t = threadIdx.x;
    int c0 = blockIdx.x * 64;
    {
        const float4* w4 = (const float4*)Wf;
        float4* d4 = (float4*)Wfs;
        for (int i = t; i < 3072; i += 256) d4[i] = w4[i];
        if (t < 256) lws[t] = lw[t];
        if (t < 4) lbs[t] = lb[t];
        if (t < 64) fbs[t] = fb[t];
    }
    __syncthreads();

    int cl = t >> 2, q = t & 3, c = c0 + cl;
    int sec = sector_ids[c];
    const float* x1 = g_seq + (size_t)c * HG;
    const float* x2 = g_sec + (size_t)sec * HG;
    const float* x3 = g_intra + (size_t)c * HG;
    float4 acc[4] = {make_float4(0,0,0,0), make_float4(0,0,0,0),
                     make_float4(0,0,0,0), make_float4(0,0,0,0)};
#pragma unroll 4
    for (int k = 0; k < HG; k++) {
        float xk = x1[k];
        const float* row = Wfs + k * HG + q * 16;
#pragma unroll
        for (int u = 0; u < 4; u++) fma4(acc[u], xk, ld4(row + 4 * u));
    }
#pragma unroll 4
    for (int k = 0; k < HG; k++) {
        float xk = x2[k];
        const float* row = Wfs + (64 + k) * HG + q * 16;
#pragma unroll
        for (int u = 0; u < 4; u++) fma4(acc[u], xk, ld4(row + 4 * u));
    }
#pragma unroll 4
    for (int k = 0; k < HG; k++) {
        float xk = x3[k];
        const float* row = Wfs + (128 + k) * HG + q * 16;
#pragma unroll
        for (int u = 0; u < 4; u++) fma4(acc[u], xk, ld4(row + 4 * u));
    }
#pragma unroll
    for (int u = 0; u < 4; u++) {
        int jb = q * 16 + 4 * u;
        float4 v = acc[u];
        v.x = fmaxf(v.x + fbs[jb], 0.f);
        v.y = fmaxf(v.y + fbs[jb + 1], 0.f);
        v.z = fmaxf(v.z + fbs[jb + 2], 0.f);
        v.w = fmaxf(v.w + fbs[jb + 3], 0.f);
        st4(fs + cl * 68 + jb, v);
    }
    __syncthreads();
    if (t < 64) {
        int c2 = c0 + t;
        float l0 = lbs[0], l1 = lbs[1], l2 = lbs[2], l3 = lbs[3];
        for (int k = 0; k < HG; k++) {
            float fv = fs[t * 68 + k];
            l0 = fmaf(fv, lws[k * 4 + 0], l0);
            l1 = fmaf(fv, lws[k * 4 + 1], l1);
            l2 = fmaf(fv, lws[k * 4 + 2], l2);
            l3 = fmaf(fv, lws[k * 4 + 3], l3);
        }
        float m = fmaxf(fmaxf(l0, l1), fmaxf(l2, l3));
        float e0 = __expf(l0 - m), e1 = __expf(l1 - m), e2 = __expf(l2 - m), e3 = __expf(l3 - m);
        float inv = 1.f / (e0 + e1 + e2 + e3);
        float p0 = e0 * inv, p1 = e1 * inv, p2 = e2 * inv, p3 = e3 * inv;
        float cA = p0, cB = cA + p1, cC = cB + p2, cD = cC + p3;
        const float EPS = 5e-8f, HI = 1.f - 5e-8f;
        float4 r;
        r.x = fminf(fmaxf(cA, EPS), HI);
        r.y = fminf(fmaxf(cB, EPS), HI);
        r.z = fminf(fmaxf(cC, EPS), HI);
        r.w = fminf(fmaxf(cD, EPS), HI);
        st4(out + (size_t)c2 * 4, r);
    }
}

// ---------------- launch ----------------
extern "C" void kernel_launch(void* const* d_in, const int* in_sizes, int n_in,
                              void* d_out, int out_size) {
    const float* daily = (const float*)d_in[0];
    const int* inner = (const int*)d_in[1];
    const int* sector = (const int*)d_in[3];
    const float* gamma = (const float*)d_in[4];
    const float* beta = (const float*)d_in[5];
    const float* Wih = (const float*)d_in[6];
    const float* Whh = (const float*)d_in[7];
    const float* bih = (const float*)d_in[8];
    const float* bhh = (const float*)d_in[9];
    const float* h0 = (const float*)d_in[10];
    const float* W1 = (const float*)d_in[11];
    const float* a1s = (const float*)d_in[12];
    const float* a1d = (const float*)d_in[13];
    const float* b1 = (const float*)d_in[14];
    const float* W2 = (const float*)d_in[15];
    const float* a2s = (const float*)d_in[16];
    const float* a2d = (const float*)d_in[17];
    const float* b2 = (const float*)d_in[18];
    const float* Wf = (const float*)d_in[19];
    const float* fb = (const float*)d_in[20];
    const float* lw = (const float*)d_in[21];
    const float* lb = (const float*)d_in[22];
    float* out = (float*)d_out;
    int E = in_sizes[1] / 2;

    cudaFuncSetAttribute(k_gru, cudaFuncAttributeMaxDynamicSharedMemorySize,
                         SM3_FLOATS * 4);
    cudaFuncSetAttribute(k_fusion, cudaFuncAttributeMaxDynamicSharedMemorySize,
                         SM9_FLOATS * 4);

    k_bn_stats<<<WIN, 256>>>(daily, gamma, beta);
    k_build_wp<<<WIN, G3>>>(Wih, bih);
    k_gru<<<NCOMP / 32, 256, SM3_FLOATS * 4>>>(daily, Whh, bhh, h0);
    k_gat1_node<<<NCOMP / 64, 256>>>(W1, a1s, a1d);
    k_deg0<<<NCOMP / 256, 256>>>();
    k_deg<<<(E + 255) / 256, 256>>>(inner, E);
    k_scan1<<<NCOMP / 256, 256>>>();
    k_scan2<<<1, 32>>>(E);
    k_scan3<<<NCOMP / 256, 256>>>();
    k_scatter<<<(E + 255) / 256, 256>>>(inner, E);
    k_agg<<<NCOMP / 8, 256>>>(b1);
    k_pool<<<NSEC, dim3(64, 4)>>>();
    k_gat2<<<1, 256>>>(W2, a2s, a2d, b2);
    k_fusion<<<NCOMP / 64, 256, SM9_FLOATS * 4>>>(sector, Wf, fb, lw, lb, out);
}

// round 6
// speedup vs baseline: 2.6210x; 2.3448x over previous
#include <cuda_runtime.h>
#include <cuda_bf16.h>
#include <cstdint>

#define NCOMP 16384
#define NSEC 64
#define PERSEC 256
#define WIN 32
#define DIN 16
#define HG 64
#define G3 192
#define EMAX 524288

// ---------------- scratch (device globals; no allocation) ----------------
__device__ float g_scale[WIN * DIN];
__device__ float g_shift[WIN * DIN];
__device__ float g_bias[WIN * G3];
__device__ float g_bnh[64];
#define WFH_U32 (2 * 4 * 24 * 64)   // [split][kt][nt][lane][2]
#define WFX_U32 (2 * 24 * 64)       // [split][nt][lane][2]
__device__ unsigned g_WhF[WFH_U32];
__device__ unsigned g_WxF[WFX_U32];
__device__ float g_seq[NCOMP * HG];
__device__ float g_h1[NCOMP * HG];
__device__ float g_ssrc[NCOMP];
__device__ float g_sdst[NCOMP];
__device__ float g_intra[NCOMP * HG];
__device__ float g_pool[NSEC * HG];
__device__ float g_sec[NSEC * HG];
__device__ int g_deg[NCOMP];
__device__ int g_off[NCOMP + 1];
__device__ int g_cursor[NCOMP];
__device__ int g_blksum[64];
__device__ int g_csr[EMAX];

// ---------------- helpers ----------------
__device__ __forceinline__ float4 ld4(const float* p) { return *(const float4*)p; }
__device__ __forceinline__ void st4(float* p, float4 v) { *(float4*)p = v; }
__device__ __forceinline__ void fma4(float4& a, float s, float4 b) {
    a.x = fmaf(s, b.x, a.x); a.y = fmaf(s, b.y, a.y);
    a.z = fmaf(s, b.z, a.z); a.w = fmaf(s, b.w, a.w);
}
__device__ __forceinline__ float lrelu(float v) { return v > 0.f ? v : 0.2f * v; }

// pack two fp32 to bf16x2 (lo half = v0), plus residual pack
__device__ __forceinline__ unsigned packbf(float v0, float v1) {
    unsigned r;
    asm("cvt.rn.bf16x2.f32 %0, %1, %2;" : "=r"(r) : "f"(v1), "f"(v0));
    return r;
}
__device__ __forceinline__ void pack_hilo(float v0, float v1, unsigned& hi, unsigned& lo) {
    unsigned hp = packbf(v0, v1);
    float h0 = __uint_as_float(hp << 16);
    float h1 = __uint_as_float(hp & 0xffff0000u);
    lo = packbf(v0 - h0, v1 - h1);
    hi = hp;
}

__device__ __forceinline__ void mma16816(float* d, const unsigned* a,
                                         unsigned b0, unsigned b1) {
    asm volatile(
        "mma.sync.aligned.m16n8k16.row.col.f32.bf16.bf16.f32 "
        "{%0,%1,%2,%3}, {%4,%5,%6,%7}, {%8,%9}, {%0,%1,%2,%3};"
        : "+f"(d[0]), "+f"(d[1]), "+f"(d[2]), "+f"(d[3])
        : "r"(a[0]), "r"(a[1]), "r"(a[2]), "r"(a[3]), "r"(b0), "r"(b1));
}

// ---------------- K1: BN stats -> scale/shift ----------------
__global__ void k_bn_stats(const float* __restrict__ daily,
                           const float* __restrict__ gamma,
                           const float* __restrict__ beta) {
    int w = blockIdx.x;
    int t = threadIdx.x, lane = t & 31, wid = t >> 5;
    float s[DIN], q[DIN];
#pragma unroll
    for (int d = 0; d < DIN; d++) { s[d] = 0.f; q[d] = 0.f; }
    const float4* base = (const float4*)(daily + (size_t)w * NCOMP * DIN);
    for (int n = t; n < NCOMP; n += 256) {
        float4 vv[4];
        vv[0] = base[n * 4 + 0]; vv[1] = base[n * 4 + 1];
        vv[2] = base[n * 4 + 2]; vv[3] = base[n * 4 + 3];
        const float* v = (const float*)vv;
#pragma unroll
        for (int d = 0; d < DIN; d++) { s[d] += v[d]; q[d] += v[d] * v[d]; }
    }
#pragma unroll
    for (int d = 0; d < DIN; d++) {
        for (int o = 16; o; o >>= 1) {
            s[d] += __shfl_down_sync(0xffffffffu, s[d], o);
            q[d] += __shfl_down_sync(0xffffffffu, q[d], o);
        }
    }
    __shared__ float S[8][DIN], Q[8][DIN];
    if (lane == 0) {
#pragma unroll
        for (int d = 0; d < DIN; d++) { S[wid][d] = s[d]; Q[wid][d] = q[d]; }
    }
    __syncthreads();
    if (t < DIN) {
        float ts = 0.f, tq = 0.f;
#pragma unroll
        for (int r = 0; r < 8; r++) { ts += S[r][t]; tq += Q[r][t]; }
        float mu = ts * (1.f / (float)NCOMP);
        float var = tq * (1.f / (float)NCOMP) - mu * mu;
        int f = w * DIN + t;
        float sc = gamma[f] * rsqrtf(var + 1e-5f);
        g_scale[f] = sc;
        g_shift[f] = beta[f] - mu * sc;
    }
}

// ---------------- K2a: per-step fused biases ----------------
__global__ void k_prep_bias(const float* __restrict__ Wih,
                            const float* __restrict__ bih,
                            const float* __restrict__ bhh) {
    int w = blockIdx.x, j = threadIdx.x;
    float acc = bih[j] + (j < 128 ? bhh[j] : 0.f);
#pragma unroll
    for (int d = 0; d < DIN; d++) acc += g_shift[w * DIN + d] * Wih[d * G3 + j];
    g_bias[w * G3 + j] = acc;
    if (w == 0 && j < 64) g_bnh[j] = bhh[128 + j];
}

// ---------------- K2b: B-fragment-ordered bf16 hi/lo weights ----------------
__global__ void k_prep_frag(const float* __restrict__ Wih,
                            const float* __restrict__ Whh) {
    int id = blockIdx.x * 256 + threadIdx.x;
    if (id < WFH_U32) {
        int r = id & 1;
        int lane = (id >> 1) & 31;
        int q = id >> 6;
        int nt = q % 24, kt = (q / 24) % 4, s = q / 96;
        int k = kt * 16 + 2 * (lane & 3) + (r ? 8 : 0);
        int n = nt * 8 + (lane >> 2);
        float v0 = Whh[k * G3 + n], v1 = Whh[(k + 1) * G3 + n];
        unsigned hi, lo;
        pack_hilo(v0, v1, hi, lo);
        g_WhF[id] = s == 0 ? hi : lo;
        return;
    }
    int id2 = id - WFH_U32;
    if (id2 < WFX_U32) {
        int r = id2 & 1;
        int lane = (id2 >> 1) & 31;
        int q = id2 >> 6;
        int nt = q % 24, s = q / 24;
        int k = 2 * (lane & 3) + (r ? 8 : 0);
        int n = nt * 8 + (lane >> 2);
        float v0 = Wih[k * G3 + n], v1 = Wih[(k + 1) * G3 + n];
        unsigned hi, lo;
        pack_hilo(v0, v1, hi, lo);
        g_WxF[id2] = s == 0 ? hi : lo;
    }
}

// ---------------- K3: HMMA GRU (warp = 16 companies, no inner syncs) ----------
#define GRU_SMEM_U32 (WFH_U32 + WFX_U32 + 6144 + 64 + 512)
__global__ void __launch_bounds__(256) k_gru_mma(const float* __restrict__ daily,
                                                 const float* __restrict__ h0) {
    extern __shared__ unsigned smu[];
    unsigned* s_WhF = smu;                      // 12288
    unsigned* s_WxF = smu + WFH_U32;            // 3072
    float* s_bias = (float*)(smu + WFH_U32 + WFX_U32);   // 6144
    float* s_bnh = s_bias + 6144;               // 64
    float* s_scale = s_bnh + 64;                // 512
    int t = threadIdx.x, lane = t & 31, warp = t >> 5;

    for (int i = t; i < WFH_U32; i += 256) s_WhF[i] = g_WhF[i];
    for (int i = t; i < WFX_U32; i += 256) s_WxF[i] = g_WxF[i];
    for (int i = t; i < 6144; i += 256) s_bias[i] = g_bias[i];
    if (t < 64) s_bnh[t] = g_bnh[t];
    for (int i = t; i < 512; i += 256) s_scale[i] = g_scale[i];
    __syncthreads();

    int row0 = blockIdx.x * 128 + warp * 16 + (lane >> 2); // rows row0, row0+8
    int colb = (lane & 3) * 2;

    // h[rh*16 + m*2 + d]  <->  h[row0+8rh][8m + colb + d]
    float h[32];
#pragma unroll
    for (int rh = 0; rh < 2; rh++) {
        const float* hp = h0 + (size_t)(row0 + rh * 8) * HG + colb;
#pragma unroll
        for (int m = 0; m < 8; m++) {
            float2 v = *(const float2*)(hp + 8 * m);
            h[rh * 16 + m * 2] = v.x;
            h[rh * 16 + m * 2 + 1] = v.y;
        }
    }

#pragma unroll 1
    for (int w = 0; w < WIN; w++) {
        // ---- x fragments (BN scale folded) ----
        unsigned ax_hi[4], ax_lo[4];
        {
            float sc0 = s_scale[w * 16 + colb], sc1 = s_scale[w * 16 + colb + 1];
            float sc8 = s_scale[w * 16 + colb + 8], sc9 = s_scale[w * 16 + colb + 9];
            const float* dw = daily + (size_t)w * NCOMP * DIN;
#pragma unroll
            for (int rh = 0; rh < 2; rh++) {
                const float* xp = dw + (size_t)(row0 + rh * 8) * DIN;
                float2 vlo = *(const float2*)(xp + colb);
                float2 vhi = *(const float2*)(xp + colb + 8);
                pack_hilo(vlo.x * sc0, vlo.y * sc1, ax_hi[rh], ax_lo[rh]);
                pack_hilo(vhi.x * sc8, vhi.y * sc9, ax_hi[2 + rh], ax_lo[2 + rh]);
            }
        }
        // ---- h fragments ----
        unsigned ah_hi[4][4], ah_lo[4][4];
#pragma unroll
        for (int kt = 0; kt < 4; kt++) {
#pragma unroll
            for (int rh = 0; rh < 2; rh++) {
                pack_hilo(h[rh * 16 + 4 * kt], h[rh * 16 + 4 * kt + 1],
                          ah_hi[kt][rh], ah_lo[kt][rh]);
                pack_hilo(h[rh * 16 + 4 * kt + 2], h[rh * 16 + 4 * kt + 3],
                          ah_hi[kt][2 + rh], ah_lo[kt][2 + rh]);
            }
        }
        // ---- accumulators ----
        float Dm[24][4], Dn[8][4];
#pragma unroll
        for (int nt = 0; nt < 24; nt++) {
            Dm[nt][0] = Dm[nt][1] = Dm[nt][2] = Dm[nt][3] = 0.f;
        }
#pragma unroll
        for (int nt = 0; nt < 8; nt++) {
            Dn[nt][0] = Dn[nt][1] = Dn[nt][2] = Dn[nt][3] = 0.f;
        }
        // ---- x @ Wih (k=16, one k-tile, 3 split terms) ----
#pragma unroll
        for (int nt = 0; nt < 24; nt++) {
            const unsigned* bh = s_WxF + nt * 64 + lane * 2;
            const unsigned* bl = s_WxF + (24 + nt) * 64 + lane * 2;
            unsigned b0 = bh[0], b1 = bh[1];
            mma16816(Dm[nt], ax_hi, b0, b1);
            mma16816(Dm[nt], ax_lo, b0, b1);
            mma16816(Dm[nt], ax_hi, bl[0], bl[1]);
        }
        // ---- h @ Whh (4 k-tiles, 3 split terms) ----
#pragma unroll
        for (int kt = 0; kt < 4; kt++) {
#pragma unroll
            for (int nt = 0; nt < 24; nt++) {
                const unsigned* bh = s_WhF + ((0 + kt) * 24 + nt) * 64 + lane * 2;
                const unsigned* bl = s_WhF + ((4 + kt) * 24 + nt) * 64 + lane * 2;
                float* D = (nt < 16) ? Dm[nt] : Dn[nt - 16];
                unsigned b0 = bh[0], b1 = bh[1];
                mma16816(D, ah_hi[kt], b0, b1);
                mma16816(D, ah_lo[kt], b0, b1);
                mma16816(D, ah_hi[kt], bl[0], bl[1]);
            }
        }
        // ---- activations ----
        const float* bw = s_bias + w * G3;
#pragma unroll
        for (int nt = 0; nt < 8; nt++) {
#pragma unroll
            for (int d = 0; d < 2; d++) {
                int j = 8 * nt + colb + d;
                float br = bw[j], bz = bw[64 + j], bn = bw[128 + j], bh2 = s_bnh[j];
#pragma unroll
                for (int rh = 0; rh < 2; rh++) {
                    int pos = rh * 2 + d;
                    float rp = Dm[nt][pos] + br;
                    float zp = Dm[8 + nt][pos] + bz;
                    float nip = Dm[16 + nt][pos] + bn;
                    float nhp = Dn[nt][pos] + bh2;
                    float r = __fdividef(1.f, 1.f + __expf(-rp));
                    float z = __fdividef(1.f, 1.f + __expf(-zp));
                    float pre = fmaf(r, nhp, nip);
                    float nn = __fdividef(2.f, 1.f + __expf(-2.f * pre)) - 1.f;
                    int hi = rh * 16 + nt * 2 + d;
                    h[hi] = fmaf(z, h[hi] - nn, nn);
                }
            }
        }
    }
    // ---- writeout ----
#pragma unroll
    for (int rh = 0; rh < 2; rh++) {
        float* op = g_seq + (size_t)(row0 + rh * 8) * HG + colb;
#pragma unroll
        for (int m = 0; m < 8; m++)
            *(float2*)(op + 8 * m) =
                make_float2(h[rh * 16 + m * 2], h[rh * 16 + m * 2 + 1]);
    }
}

// ---------------- K4: GAT1 node transform + attention dots ----------------
__global__ void k_gat1_node(const float* __restrict__ W1,
                            const float* __restrict__ a1s,
                            const float* __restrict__ a1d) {
    __shared__ float W1s[HG * HG];
    __shared__ float xs[64 * 65];
    __shared__ float as_s[HG], ad_s[HG];
    int t = threadIdx.x;
    int c0 = blockIdx.x * 64;
    for (int i = t; i < HG * HG; i += 256) W1s[i] = W1[i];
    for (int i = t; i < 64 * HG; i += 256) {
        int cc = i >> 6, k = i & 63;
        xs[cc * 65 + k] = g_seq[(size_t)(c0 + cc) * HG + k];
    }
    if (t < HG) { as_s[t] = a1s[t]; ad_s[t] = a1d[t]; }
    __syncthreads();

    int cl = t >> 2, q = t & 3, c = c0 + cl;
    float4 acc[4] = {make_float4(0,0,0,0), make_float4(0,0,0,0),
                     make_float4(0,0,0,0), make_float4(0,0,0,0)};
#pragma unroll 8
    for (int k = 0; k < HG; k++) {
        float x = xs[cl * 65 + k];
        const float* row = W1s + k * HG + q * 16;
#pragma unroll
        for (int u = 0; u < 4; u++) fma4(acc[u], x, ld4(row + 4 * u));
    }
    float ps = 0.f, pd = 0.f;
#pragma unroll
    for (int u = 0; u < 4; u++) {
        int jb = q * 16 + 4 * u;
        const float* a = (const float*)&acc[u];
#pragma unroll
        for (int e = 0; e < 4; e++) {
            ps += a[e] * as_s[jb + e];
            pd += a[e] * ad_s[jb + e];
        }
        st4(g_h1 + (size_t)c * HG + jb, acc[u]);
    }
    ps += __shfl_xor_sync(0xffffffffu, ps, 1);
    ps += __shfl_xor_sync(0xffffffffu, ps, 2);
    pd += __shfl_xor_sync(0xffffffffu, pd, 1);
    pd += __shfl_xor_sync(0xffffffffu, pd, 2);
    if (q == 0) { g_ssrc[c] = ps; g_sdst[c] = pd; }
}

// ---------------- CSR build ----------------
__global__ void k_deg0() { g_deg[blockIdx.x * 256 + threadIdx.x] = 0; }
__global__ void k_deg(const int* __restrict__ e, int E) {
    int i = blockIdx.x * 256 + threadIdx.x;
    if (i < E) atomicAdd(&g_deg[e[E + i]], 1);
}
__global__ void k_scan1() {
    __shared__ int s[256];
    int b = blockIdx.x, t = threadIdx.x, i = b * 256 + t;
    int d = g_deg[i];
    s[t] = d;
    __syncthreads();
    for (int o = 1; o < 256; o <<= 1) {
        int v = (t >= o) ? s[t - o] : 0;
        __syncthreads();
        s[t] += v;
        __syncthreads();
    }
    g_off[i] = s[t] - d;
    if (t == 255) g_blksum[b] = s[255];
}
__global__ void k_scan2(int E) {
    if (threadIdx.x == 0) {
        int a = 0;
        for (int b = 0; b < 64; b++) { int v = g_blksum[b]; g_blksum[b] = a; a += v; }
        g_off[NCOMP] = E;
    }
}
__global__ void k_scan3() {
    int b = blockIdx.x, i = b * 256 + threadIdx.x;
    int o = g_off[i] + g_blksum[b];
    g_off[i] = o;
    g_cursor[i] = o;
}
__global__ void k_scatter(const int* __restrict__ e, int E) {
    int i = blockIdx.x * 256 + threadIdx.x;
    if (i < E) {
        int d = e[E + i];
        int p = atomicAdd(&g_cursor[d], 1);
        if (p < EMAX) g_csr[p] = e[i];
    }
}

// ---------------- K6: warp-per-dst online softmax aggregate ----------------
__global__ void k_agg(const float* __restrict__ b1) {
    int gw = (blockIdx.x * 256 + threadIdx.x) >> 5;
    int lane = threadIdx.x & 31;
    int dst = gw;
    float sd = g_sdst[dst];
    float m = lrelu(g_ssrc[dst] + sd);
    float den = 1.f;
    float a0 = g_h1[(size_t)dst * HG + lane];
    float a1 = g_h1[(size_t)dst * HG + lane + 32];
    int s = g_off[dst], e = g_off[dst + 1];
    for (int base = s; base < e; base += 32) {
        int p = base + lane;
        bool valid = p < e;
        int src = valid ? g_csr[p] : 0;
        float ev = valid ? lrelu(g_ssrc[src] + sd) : -3.4e38f;
        float cm = ev;
        for (int o = 16; o; o >>= 1)
            cm = fmaxf(cm, __shfl_xor_sync(0xffffffffu, cm, o));
        if (cm > m) {
            float f = __expf(m - cm);
            a0 *= f; a1 *= f; den *= f;
            m = cm;
        }
        int cnt = min(32, e - base);
        for (int j = 0; j < cnt; j++) {
            int sj = __shfl_sync(0xffffffffu, src, j);
            float ej = __shfl_sync(0xffffffffu, ev, j);
            float wj = __expf(ej - m);
            den += wj;
            a0 = fmaf(wj, g_h1[(size_t)sj * HG + lane], a0);
            a1 = fmaf(wj, g_h1[(size_t)sj * HG + lane + 32], a1);
        }
    }
    float inv = __fdividef(1.f, den + 1e-16f);
    g_intra[(size_t)dst * HG + lane] = a0 * inv + b1[lane];
    g_intra[(size_t)dst * HG + lane + 32] = a1 * inv + b1[lane + 32];
}

// ---------------- K7b: sector max pool ----------------
__global__ void k_pool() {
    int s = blockIdx.x;
    int tx = threadIdx.x, ty = threadIdx.y;
    float m = -3.4e38f;
    for (int cc = ty; cc < PERSEC; cc += 4)
        m = fmaxf(m, g_intra[((size_t)(s * PERSEC + cc)) * HG + tx]);
    __shared__ float red[4][64];
    red[ty][tx] = m;
    __syncthreads();
    if (ty == 0) {
        m = fmaxf(fmaxf(red[0][tx], red[1][tx]), fmaxf(red[2][tx], red[3][tx]));
        g_pool[s * HG + tx] = m;
    }
}

// ---------------- K8: GAT2 on 64 sectors (dense, one block) ----------------
__global__ void k_gat2(const float* __restrict__ W2,
                       const float* __restrict__ a2s,
                       const float* __restrict__ a2d,
                       const float* __restrict__ b2) {
    __shared__ float W2s[HG * HG];
    __shared__ float h2s[64 * 68];
    __shared__ float ss[64], sd[64], as_s[64], ad_s[64];
    int t = threadIdx.x;
    for (int i = t; i < HG * HG; i += 256) W2s[i] = W2[i];
    if (t < 64) { as_s[t] = a2s[t]; ad_s[t] = a2d[t]; }
    __syncthreads();

    int i = t >> 2, q = t & 3;
    {
        float4 acc[4] = {make_float4(0,0,0,0), make_float4(0,0,0,0),
                         make_float4(0,0,0,0), make_float4(0,0,0,0)};
        for (int k = 0; k < HG; k++) {
            float x = g_pool[i * HG + k];
            const float* row = W2s + k * HG + q * 16;
#pragma unroll
            for (int u = 0; u < 4; u++) fma4(acc[u], x, ld4(row + 4 * u));
        }
#pragma unroll
        for (int u = 0; u < 4; u++) st4(h2s + i * 68 + q * 16 + 4 * u, acc[u]);
    }
    __syncthreads();
    if (t < 64) {
        float s1 = 0.f, s2 = 0.f;
        for (int k = 0; k < HG; k++) {
            float v = h2s[t * 68 + k];
            s1 += v * as_s[k]; s2 += v * ad_s[k];
        }
        ss[t] = s1; sd[t] = s2;
    }
    __syncthreads();
    {
        int wi = t >> 5, lane = t & 31;
        for (int dst = wi; dst < 64; dst += 8) {
            float e1 = lrelu(ss[lane] + sd[dst]);
            float e2 = lrelu(ss[lane + 32] + sd[dst]);
            float m = fmaxf(e1, e2);
            for (int o = 16; o; o >>= 1) m = fmaxf(m, __shfl_xor_sync(0xffffffffu, m, o));
            float w1 = __expf(e1 - m), w2 = __expf(e2 - m);
            float s = w1 + w2;
            for (int o = 16; o; o >>= 1) s += __shfl_xor_sync(0xffffffffu, s, o);
            float inv = 1.f / (s + 1e-16f);
            W2s[dst * 64 + lane] = w1 * inv;
            W2s[dst * 64 + lane + 32] = w2 * inv;
        }
    }
    __syncthreads();
    {
        int dst = i;
        float4 o[4] = {make_float4(0,0,0,0), make_float4(0,0,0,0),
                       make_float4(0,0,0,0), make_float4(0,0,0,0)};
        for (int src = 0; src < 64; src++) {
            float a = W2s[dst * 64 + src];
            const float* row = h2s + src * 68 + q * 16;
#pragma unroll
            for (int u = 0; u < 4; u++) fma4(o[u], a, ld4(row + 4 * u));
        }
#pragma unroll
        for (int u = 0; u < 4; u++) {
            int jb = q * 16 + 4 * u;
            float4 v = o[u];
            v.x += b2[jb]; v.y += b2[jb + 1]; v.z += b2[jb + 2]; v.w += b2[jb + 3];
            st4(g_sec + dst * HG + jb, v);
        }
    }
}

// ---------------- K9: fusion + logits + softmax/cumsum/clip ----------------
#define SM9_FLOATS (12288 + 64 * 68 + 256 + 4 + 64)
__global__ void k_fusion(const int* __restrict__ sector_ids,
                         const float* __restrict__ Wf,
                         const float* __restrict__ fb,
                         const float* __restrict__ lw,
                         const float* __restrict__ lb,
                         float* __restrict__ out) {
    extern __shared__ float sm[];
    float* Wfs = sm;
    float* fs  = sm + 12288;
    float* lws = sm + 12288 + 64 * 68;
    float* lbs = lws + 256;
    float* fbs = lbs + 4;
    int t = threadIdx.x;
    int c0 = blockIdx.x * 64;
    {
        const float4* w4 = (const float4*)Wf;
        float4* d4 = (float4*)Wfs;
        for (int i = t; i < 3072; i += 256) d4[i] = w4[i];
        if (t < 256) lws[t] = lw[t];
        if (t < 4) lbs[t] = lb[t];
        if (t < 64) fbs[t] = fb[t];
    }
    __syncthreads();

    int cl = t >> 2, q = t & 3, c = c0 + cl;
    int sec = sector_ids[c];
    const float* x1 = g_seq + (size_t)c * HG;
    const float* x2 = g_sec + (size_t)sec * HG;
    const float* x3 = g_intra + (size_t)c * HG;
    float4 acc[4] = {make_float4(0,0,0,0), make_float4(0,0,0,0),
                     make_float4(0,0,0,0), make_float4(0,0,0,0)};
#pragma unroll 4
    for (int k = 0; k < HG; k++) {
        float xk = x1[k];
        const float* row = Wfs + k * HG + q * 16;
#pragma unroll
        for (int u = 0; u < 4; u++) fma4(acc[u], xk, ld4(row + 4 * u));
    }
#pragma unroll 4
    for (int k = 0; k < HG; k++) {
        float xk = x2[k];
        const float* row = Wfs + (64 + k) * HG + q * 16;
#pragma unroll
        for (int u = 0; u < 4; u++) fma4(acc[u], xk, ld4(row + 4 * u));
    }
#pragma unroll 4
    for (int k = 0; k < HG; k++) {
        float xk = x3[k];
        const float* row = Wfs + (128 + k) * HG + q * 16;
#pragma unroll
        for (int u = 0; u < 4; u++) fma4(acc[u], xk, ld4(row + 4 * u));
    }
#pragma unroll
    for (int u = 0; u < 4; u++) {
        int jb = q * 16 + 4 * u;
        float4 v = acc[u];
        v.x = fmaxf(v.x + fbs[jb], 0.f);
        v.y = fmaxf(v.y + fbs[jb + 1], 0.f);
        v.z = fmaxf(v.z + fbs[jb + 2], 0.f);
        v.w = fmaxf(v.w + fbs[jb + 3], 0.f);
        st4(fs + cl * 68 + jb, v);
    }
    __syncthreads();
    if (t < 64) {
        int c2 = c0 + t;
        float l0 = lbs[0], l1 = lbs[1], l2 = lbs[2], l3 = lbs[3];
        for (int k = 0; k < HG; k++) {
            float fv = fs[t * 68 + k];
            l0 = fmaf(fv, lws[k * 4 + 0], l0);
            l1 = fmaf(fv, lws[k * 4 + 1], l1);
            l2 = fmaf(fv, lws[k * 4 + 2], l2);
            l3 = fmaf(fv, lws[k * 4 + 3], l3);
        }
        float m = fmaxf(fmaxf(l0, l1), fmaxf(l2, l3));
        float e0 = __expf(l0 - m), e1 = __expf(l1 - m), e2 = __expf(l2 - m), e3 = __expf(l3 - m);
        float inv = 1.f / (e0 + e1 + e2 + e3);
        float p0 = e0 * inv, p1 = e1 * inv, p2 = e2 * inv, p3 = e3 * inv;
        float cA = p0, cB = cA + p1, cC = cB + p2, cD = cC + p3;
        const float EPS = 5e-8f, HI = 1.f - 5e-8f;
        float4 r;
        r.x = fminf(fmaxf(cA, EPS), HI);
        r.y = fminf(fmaxf(cB, EPS), HI);
        r.z = fminf(fmaxf(cC, EPS), HI);
        r.w = fminf(fmaxf(cD, EPS), HI);
        st4(out + (size_t)c2 * 4, r);
    }
}

// ---------------- launch ----------------
extern "C" void kernel_launch(void* const* d_in, const int* in_sizes, int n_in,
                              void* d_out, int out_size) {
    const float* daily = (const float*)d_in[0];
    const int* inner = (const int*)d_in[1];
    const int* sector = (const int*)d_in[3];
    const float* gamma = (const float*)d_in[4];
    const float* beta = (const float*)d_in[5];
    const float* Wih = (const float*)d_in[6];
    const float* Whh = (const float*)d_in[7];
    const float* bih = (const float*)d_in[8];
    const float* bhh = (const float*)d_in[9];
    const float* h0 = (const float*)d_in[10];
    const float* W1 = (const float*)d_in[11];
    const float* a1s = (const float*)d_in[12];
    const float* a1d = (const float*)d_in[13];
    const float* b1 = (const float*)d_in[14];
    const float* W2 = (const float*)d_in[15];
    const float* a2s = (const float*)d_in[16];
    const float* a2d = (const float*)d_in[17];
    const float* b2 = (const float*)d_in[18];
    const float* Wf = (const float*)d_in[19];
    const float* fb = (const float*)d_in[20];
    const float* lw = (const float*)d_in[21];
    const float* lb = (const float*)d_in[22];
    float* out = (float*)d_out;
    int E = in_sizes[1] / 2;

    cudaFuncSetAttribute(k_gru_mma, cudaFuncAttributeMaxDynamicSharedMemorySize,
                         GRU_SMEM_U32 * 4);
    cudaFuncSetAttribute(k_fusion, cudaFuncAttributeMaxDynamicSharedMemorySize,
                         SM9_FLOATS * 4);

    k_bn_stats<<<WIN, 256>>>(daily, gamma, beta);
    k_prep_bias<<<WIN, G3>>>(Wih, bih, bhh);
    k_prep_frag<<<(WFH_U32 + WFX_U32 + 255) / 256, 256>>>(Wih, Whh);
    k_gru_mma<<<NCOMP / 128, 256, GRU_SMEM_U32 * 4>>>(daily, h0);
    k_gat1_node<<<NCOMP / 64, 256>>>(W1, a1s, a1d);
    k_deg0<<<NCOMP / 256, 256>>>();
    k_deg<<<(E + 255) / 256, 256>>>(inner, E);
    k_scan1<<<NCOMP / 256, 256>>>();
    k_scan2<<<1, 32>>>(E);
    k_scan3<<<NCOMP / 256, 256>>>();
    k_scatter<<<(E + 255) / 256, 256>>>(inner, E);
    k_agg<<<NCOMP / 8, 256>>>(b1);
    k_pool<<<NSEC, dim3(64, 4)>>>();
    k_gat2<<<1, 256>>>(W2, a2s, a2d, b2);
    k_fusion<<<NCOMP / 64, 256, SM9_FLOATS * 4>>>(sector, Wf, fb, lw, lb, out);
}

// round 7
// speedup vs baseline: 3.0832x; 1.1763x over previous
#include <cuda_runtime.h>
#include <cuda_bf16.h>
#include <cstdint>

#define NCOMP 16384
#define NSEC 64
#define PERSEC 256
#define WIN 32
#define DIN 16
#define HG 64
#define G3 192
#define EMAX 524288

// ---------------- scratch (device globals; no allocation) ----------------
__device__ float g_bnpartS[WIN * 8 * DIN];
__device__ float g_bnpartQ[WIN * 8 * DIN];
__device__ float g_scale[WIN * DIN];
__device__ float g_shift[WIN * DIN];
__device__ float g_bias[WIN * G3];
__device__ float g_bnh[64];
#define WFH_U32 (2 * 4 * 24 * 64)   // GRU Whh frags
#define WFX_U32 (2 * 24 * 64)       // GRU Wih frags
#define W1F_U32 (2 * 4 * 8 * 64)    // GAT1 W frags
#define WFF_U32 (2 * 12 * 8 * 64)   // fusion W frags
__device__ unsigned g_WhF[WFH_U32];
__device__ unsigned g_WxF[WFX_U32];
__device__ unsigned g_W1F[W1F_U32];
__device__ unsigned g_WfF[WFF_U32];
__device__ float g_seq[NCOMP * HG];
__device__ float g_h1[NCOMP * HG];
__device__ float g_ssrc[NCOMP];
__device__ float g_sdst[NCOMP];
__device__ float g_intra[NCOMP * HG];
__device__ float g_pool[NSEC * HG];
__device__ float g_sec[NSEC * HG];
__device__ int g_deg[NCOMP];
__device__ int g_off[NCOMP + 1];
__device__ int g_cursor[NCOMP];
__device__ int g_blksum[64];
__device__ int g_csr[EMAX];

// ---------------- helpers ----------------
__device__ __forceinline__ float4 ld4(const float* p) { return *(const float4*)p; }
__device__ __forceinline__ void st4(float* p, float4 v) { *(float4*)p = v; }
__device__ __forceinline__ void fma4(float4& a, float s, float4 b) {
    a.x = fmaf(s, b.x, a.x); a.y = fmaf(s, b.y, a.y);
    a.z = fmaf(s, b.z, a.z); a.w = fmaf(s, b.w, a.w);
}
__device__ __forceinline__ float lrelu(float v) { return v > 0.f ? v : 0.2f * v; }

__device__ __forceinline__ unsigned packbf(float v0, float v1) {
    unsigned r;
    asm("cvt.rn.bf16x2.f32 %0, %1, %2;" : "=r"(r) : "f"(v1), "f"(v0));
    return r;
}
__device__ __forceinline__ void pack_hilo(float v0, float v1, unsigned& hi, unsigned& lo) {
    unsigned hp = packbf(v0, v1);
    float h0 = __uint_as_float(hp << 16);
    float h1 = __uint_as_float(hp & 0xffff0000u);
    lo = packbf(v0 - h0, v1 - h1);
    hi = hp;
}
__device__ __forceinline__ void mma16816(float* d, const unsigned* a,
                                         unsigned b0, unsigned b1) {
    asm volatile(
        "mma.sync.aligned.m16n8k16.row.col.f32.bf16.bf16.f32 "
        "{%0,%1,%2,%3}, {%4,%5,%6,%7}, {%8,%9}, {%0,%1,%2,%3};"
        : "+f"(d[0]), "+f"(d[1]), "+f"(d[2]), "+f"(d[3])
        : "r"(a[0]), "r"(a[1]), "r"(a[2]), "r"(a[3]), "r"(b0), "r"(b1));
}

// ---------------- K1a: BN partial sums (grid WIN x 8, deterministic) --------
__global__ void k_bn_stats(const float* __restrict__ daily) {
    int w = blockIdx.x, by = blockIdx.y;
    int t = threadIdx.x, lane = t & 31, wid = t >> 5;
    float s[DIN], q[DIN];
#pragma unroll
    for (int d = 0; d < DIN; d++) { s[d] = 0.f; q[d] = 0.f; }
    const float4* base =
        (const float4*)(daily + ((size_t)w * NCOMP + by * 2048) * DIN);
    for (int n = t; n < 2048; n += 256) {
        float4 vv[4];
        vv[0] = base[n * 4 + 0]; vv[1] = base[n * 4 + 1];
        vv[2] = base[n * 4 + 2]; vv[3] = base[n * 4 + 3];
        const float* v = (const float*)vv;
#pragma unroll
        for (int d = 0; d < DIN; d++) { s[d] += v[d]; q[d] += v[d] * v[d]; }
    }
#pragma unroll
    for (int d = 0; d < DIN; d++) {
        for (int o = 16; o; o >>= 1) {
            s[d] += __shfl_down_sync(0xffffffffu, s[d], o);
            q[d] += __shfl_down_sync(0xffffffffu, q[d], o);
        }
    }
    __shared__ float S[8][DIN], Q[8][DIN];
    if (lane == 0) {
#pragma unroll
        for (int d = 0; d < DIN; d++) { S[wid][d] = s[d]; Q[wid][d] = q[d]; }
    }
    __syncthreads();
    if (t < DIN) {
        float ts = 0.f, tq = 0.f;
#pragma unroll
        for (int r = 0; r < 8; r++) { ts += S[r][t]; tq += Q[r][t]; }
        g_bnpartS[(w * 8 + by) * DIN + t] = ts;
        g_bnpartQ[(w * 8 + by) * DIN + t] = tq;
    }
}

// ---------------- K1b: finalize scale/shift ----------------
__global__ void k_bn_fin(const float* __restrict__ gamma,
                         const float* __restrict__ beta) {
    int f = blockIdx.x * 256 + threadIdx.x;
    if (f >= WIN * DIN) return;
    int w = f / DIN, d = f % DIN;
    float ts = 0.f, tq = 0.f;
#pragma unroll
    for (int by = 0; by < 8; by++) {
        ts += g_bnpartS[(w * 8 + by) * DIN + d];
        tq += g_bnpartQ[(w * 8 + by) * DIN + d];
    }
    float mu = ts * (1.f / (float)NCOMP);
    float var = tq * (1.f / (float)NCOMP) - mu * mu;
    float sc = gamma[f] * rsqrtf(var + 1e-5f);
    g_scale[f] = sc;
    g_shift[f] = beta[f] - mu * sc;
}

// ---------------- K2a: per-step fused biases ----------------
__global__ void k_prep_bias(const float* __restrict__ Wih,
                            const float* __restrict__ bih,
                            const float* __restrict__ bhh) {
    int w = blockIdx.x, j = threadIdx.x;
    float acc = bih[j] + (j < 128 ? bhh[j] : 0.f);
#pragma unroll
    for (int d = 0; d < DIN; d++) acc += g_shift[w * DIN + d] * Wih[d * G3 + j];
    g_bias[w * G3 + j] = acc;
    if (w == 0 && j < 64) g_bnh[j] = bhh[128 + j];
}

// ---------------- K2b: GRU fragment weights ----------------
__global__ void k_prep_frag(const float* __restrict__ Wih,
                            const float* __restrict__ Whh) {
    int id = blockIdx.x * 256 + threadIdx.x;
    if (id < WFH_U32) {
        int r = id & 1;
        int lane = (id >> 1) & 31;
        int q = id >> 6;
        int nt = q % 24, kt = (q / 24) % 4, s = q / 96;
        int k = kt * 16 + 2 * (lane & 3) + (r ? 8 : 0);
        int n = nt * 8 + (lane >> 2);
        float v0 = Whh[k * G3 + n], v1 = Whh[(k + 1) * G3 + n];
        unsigned hi, lo;
        pack_hilo(v0, v1, hi, lo);
        g_WhF[id] = s == 0 ? hi : lo;
        return;
    }
    int id2 = id - WFH_U32;
    if (id2 < WFX_U32) {
        int r = id2 & 1;
        int lane = (id2 >> 1) & 31;
        int q = id2 >> 6;
        int nt = q % 24, s = q / 24;
        int k = 2 * (lane & 3) + (r ? 8 : 0);
        int n = nt * 8 + (lane >> 2);
        float v0 = Wih[k * G3 + n], v1 = Wih[(k + 1) * G3 + n];
        unsigned hi, lo;
        pack_hilo(v0, v1, hi, lo);
        g_WxF[id2] = s == 0 ? hi : lo;
    }
}

// ---------------- K2c: GAT1 + fusion fragment weights ----------------
__global__ void k_prep_frag2(const float* __restrict__ W1,
                             const float* __restrict__ Wf) {
    int id = blockIdx.x * 256 + threadIdx.x;
    if (id < W1F_U32) {
        int r = id & 1, lane = (id >> 1) & 31, q = id >> 6;
        int nt = q % 8, kt = (q / 8) % 4, s = q / 32;
        int k = kt * 16 + 2 * (lane & 3) + (r ? 8 : 0);
        int n = nt * 8 + (lane >> 2);
        float v0 = W1[k * HG + n], v1 = W1[(k + 1) * HG + n];
        unsigned hi, lo;
        pack_hilo(v0, v1, hi, lo);
        g_W1F[id] = s ? lo : hi;
        return;
    }
    int i2 = id - W1F_U32;
    if (i2 < WFF_U32) {
        int r = i2 & 1, lane = (i2 >> 1) & 31, q = i2 >> 6;
        int nt = q % 8, kt = (q / 8) % 12, s = q / 96;
        int k = kt * 16 + 2 * (lane & 3) + (r ? 8 : 0);
        int n = nt * 8 + (lane >> 2);
        float v0 = Wf[k * HG + n], v1 = Wf[(k + 1) * HG + n];
        unsigned hi, lo;
        pack_hilo(v0, v1, hi, lo);
        g_WfF[i2] = s ? lo : hi;
    }
}

// ---------------- K3: HMMA GRU (unchanged from round 6) ----------------
#define GRU_SMEM_U32 (WFH_U32 + WFX_U32 + 6144 + 64 + 512)
__global__ void __launch_bounds__(256) k_gru_mma(const float* __restrict__ daily,
                                                 const float* __restrict__ h0) {
    extern __shared__ unsigned smu[];
    unsigned* s_WhF = smu;
    unsigned* s_WxF = smu + WFH_U32;
    float* s_bias = (float*)(smu + WFH_U32 + WFX_U32);
    float* s_bnh = s_bias + 6144;
    float* s_scale = s_bnh + 64;
    int t = threadIdx.x, lane = t & 31, warp = t >> 5;

    for (int i = t; i < WFH_U32; i += 256) s_WhF[i] = g_WhF[i];
    for (int i = t; i < WFX_U32; i += 256) s_WxF[i] = g_WxF[i];
    for (int i = t; i < 6144; i += 256) s_bias[i] = g_bias[i];
    if (t < 64) s_bnh[t] = g_bnh[t];
    for (int i = t; i < 512; i += 256) s_scale[i] = g_scale[i];
    __syncthreads();

    int row0 = blockIdx.x * 128 + warp * 16 + (lane >> 2);
    int colb = (lane & 3) * 2;

    float h[32];
#pragma unroll
    for (int rh = 0; rh < 2; rh++) {
        const float* hp = h0 + (size_t)(row0 + rh * 8) * HG + colb;
#pragma unroll
        for (int m = 0; m < 8; m++) {
            float2 v = *(const float2*)(hp + 8 * m);
            h[rh * 16 + m * 2] = v.x;
            h[rh * 16 + m * 2 + 1] = v.y;
        }
    }

#pragma unroll 1
    for (int w = 0; w < WIN; w++) {
        unsigned ax_hi[4], ax_lo[4];
        {
            float sc0 = s_scale[w * 16 + colb], sc1 = s_scale[w * 16 + colb + 1];
            float sc8 = s_scale[w * 16 + colb + 8], sc9 = s_scale[w * 16 + colb + 9];
            const float* dw = daily + (size_t)w * NCOMP * DIN;
#pragma unroll
            for (int rh = 0; rh < 2; rh++) {
                const float* xp = dw + (size_t)(row0 + rh * 8) * DIN;
                float2 vlo = *(const float2*)(xp + colb);
                float2 vhi = *(const float2*)(xp + colb + 8);
                pack_hilo(vlo.x * sc0, vlo.y * sc1, ax_hi[rh], ax_lo[rh]);
                pack_hilo(vhi.x * sc8, vhi.y * sc9, ax_hi[2 + rh], ax_lo[2 + rh]);
            }
        }
        unsigned ah_hi[4][4], ah_lo[4][4];
#pragma unroll
        for (int kt = 0; kt < 4; kt++) {
#pragma unroll
            for (int rh = 0; rh < 2; rh++) {
                pack_hilo(h[rh * 16 + 4 * kt], h[rh * 16 + 4 * kt + 1],
                          ah_hi[kt][rh], ah_lo[kt][rh]);
                pack_hilo(h[rh * 16 + 4 * kt + 2], h[rh * 16 + 4 * kt + 3],
                          ah_hi[kt][2 + rh], ah_lo[kt][2 + rh]);
            }
        }
        float Dm[24][4], Dn[8][4];
#pragma unroll
        for (int nt = 0; nt < 24; nt++)
            Dm[nt][0] = Dm[nt][1] = Dm[nt][2] = Dm[nt][3] = 0.f;
#pragma unroll
        for (int nt = 0; nt < 8; nt++)
            Dn[nt][0] = Dn[nt][1] = Dn[nt][2] = Dn[nt][3] = 0.f;
#pragma unroll
        for (int nt = 0; nt < 24; nt++) {
            const unsigned* bh = s_WxF + nt * 64 + lane * 2;
            const unsigned* bl = s_WxF + (24 + nt) * 64 + lane * 2;
            unsigned b0 = bh[0], b1 = bh[1];
            mma16816(Dm[nt], ax_hi, b0, b1);
            mma16816(Dm[nt], ax_lo, b0, b1);
            mma16816(Dm[nt], ax_hi, bl[0], bl[1]);
        }
#pragma unroll
        for (int kt = 0; kt < 4; kt++) {
#pragma unroll
            for (int nt = 0; nt < 24; nt++) {
                const unsigned* bh = s_WhF + ((0 + kt) * 24 + nt) * 64 + lane * 2;
                const unsigned* bl = s_WhF + ((4 + kt) * 24 + nt) * 64 + lane * 2;
                float* D = (nt < 16) ? Dm[nt] : Dn[nt - 16];
                unsigned b0 = bh[0], b1 = bh[1];
                mma16816(D, ah_hi[kt], b0, b1);
                mma16816(D, ah_lo[kt], b0, b1);
                mma16816(D, ah_hi[kt], bl[0], bl[1]);
            }
        }
        const float* bw = s_bias + w * G3;
#pragma unroll
        for (int nt = 0; nt < 8; nt++) {
#pragma unroll
            for (int d = 0; d < 2; d++) {
                int j = 8 * nt + colb + d;
                float br = bw[j], bz = bw[64 + j], bn = bw[128 + j], bh2 = s_bnh[j];
#pragma unroll
                for (int rh = 0; rh < 2; rh++) {
                    int pos = rh * 2 + d;
                    float rp = Dm[nt][pos] + br;
                    float zp = Dm[8 + nt][pos] + bz;
                    float nip = Dm[16 + nt][pos] + bn;
                    float nhp = Dn[nt][pos] + bh2;
                    float r = __fdividef(1.f, 1.f + __expf(-rp));
                    float z = __fdividef(1.f, 1.f + __expf(-zp));
                    float pre = fmaf(r, nhp, nip);
                    float nn = __fdividef(2.f, 1.f + __expf(-2.f * pre)) - 1.f;
                    int hi = rh * 16 + nt * 2 + d;
                    h[hi] = fmaf(z, h[hi] - nn, nn);
                }
            }
        }
    }
#pragma unroll
    for (int rh = 0; rh < 2; rh++) {
        float* op = g_seq + (size_t)(row0 + rh * 8) * HG + colb;
#pragma unroll
        for (int m = 0; m < 8; m++)
            *(float2*)(op + 8 * m) =
                make_float2(h[rh * 16 + m * 2], h[rh * 16 + m * 2 + 1]);
    }
}

// ---------------- K4: HMMA GAT1 node transform + attention dots -------------
__global__ void __launch_bounds__(256) k_gat1_mma(const float* __restrict__ a1s,
                                                  const float* __restrict__ a1d) {
    __shared__ unsigned sW[W1F_U32];
    __shared__ float as_s[64], ad_s[64];
    int t = threadIdx.x, lane = t & 31, warp = t >> 5;
    for (int i = t; i < W1F_U32; i += 256) sW[i] = g_W1F[i];
    if (t < 64) { as_s[t] = a1s[t]; ad_s[t] = a1d[t]; }
    __syncthreads();

    int row0 = blockIdx.x * 128 + warp * 16 + (lane >> 2);
    int colq = 2 * (lane & 3);

    unsigned ah[4][4], al[4][4];
#pragma unroll
    for (int kt = 0; kt < 4; kt++) {
#pragma unroll
        for (int rh = 0; rh < 2; rh++) {
            const float* sp = g_seq + (size_t)(row0 + rh * 8) * HG + kt * 16 + colq;
            float2 v0 = *(const float2*)sp;
            float2 v1 = *(const float2*)(sp + 8);
            pack_hilo(v0.x, v0.y, ah[kt][rh], al[kt][rh]);
            pack_hilo(v1.x, v1.y, ah[kt][2 + rh], al[kt][2 + rh]);
        }
    }
    float D[8][4];
#pragma unroll
    for (int nt = 0; nt < 8; nt++) D[nt][0] = D[nt][1] = D[nt][2] = D[nt][3] = 0.f;
#pragma unroll
    for (int kt = 0; kt < 4; kt++) {
#pragma unroll
        for (int nt = 0; nt < 8; nt++) {
            const unsigned* bh = sW + ((0 + kt) * 8 + nt) * 64 + lane * 2;
            const unsigned* bl = sW + ((4 + kt) * 8 + nt) * 64 + lane * 2;
            unsigned b0 = bh[0], b1 = bh[1];
            mma16816(D[nt], ah[kt], b0, b1);
            mma16816(D[nt], al[kt], b0, b1);
            mma16816(D[nt], ah[kt], bl[0], bl[1]);
        }
    }
    float ps[2] = {0.f, 0.f}, pd[2] = {0.f, 0.f};
#pragma unroll
    for (int nt = 0; nt < 8; nt++) {
#pragma unroll
        for (int rh = 0; rh < 2; rh++) {
            int col = 8 * nt + colq;
            float v0 = D[nt][rh * 2], v1 = D[nt][rh * 2 + 1];
            ps[rh] += v0 * as_s[col] + v1 * as_s[col + 1];
            pd[rh] += v0 * ad_s[col] + v1 * ad_s[col + 1];
            *(float2*)(g_h1 + (size_t)(row0 + rh * 8) * HG + col) =
                make_float2(v0, v1);
        }
    }
#pragma unroll
    for (int rh = 0; rh < 2; rh++) {
        ps[rh] += __shfl_xor_sync(0xffffffffu, ps[rh], 1);
        ps[rh] += __shfl_xor_sync(0xffffffffu, ps[rh], 2);
        pd[rh] += __shfl_xor_sync(0xffffffffu, pd[rh], 1);
        pd[rh] += __shfl_xor_sync(0xffffffffu, pd[rh], 2);
    }
    if ((lane & 3) == 0) {
        g_ssrc[row0] = ps[0]; g_ssrc[row0 + 8] = ps[1];
        g_sdst[row0] = pd[0]; g_sdst[row0 + 8] = pd[1];
    }
}

// ---------------- CSR build ----------------
__global__ void k_deg0() { g_deg[blockIdx.x * 256 + threadIdx.x] = 0; }
__global__ void k_deg(const int* __restrict__ e, int E) {
    int i = blockIdx.x * 256 + threadIdx.x;
    if (i < E) atomicAdd(&g_deg[e[E + i]], 1);
}
__global__ void k_scan1() {
    __shared__ int s[256];
    int b = blockIdx.x, t = threadIdx.x, i = b * 256 + t;
    int d = g_deg[i];
    s[t] = d;
    __syncthreads();
    for (int o = 1; o < 256; o <<= 1) {
        int v = (t >= o) ? s[t - o] : 0;
        __syncthreads();
        s[t] += v;
        __syncthreads();
    }
    g_off[i] = s[t] - d;
    if (t == 255) g_blksum[b] = s[255];
}
__global__ void k_scan2(int E) {
    if (threadIdx.x == 0) {
        int a = 0;
        for (int b = 0; b < 64; b++) { int v = g_blksum[b]; g_blksum[b] = a; a += v; }
        g_off[NCOMP] = E;
    }
}
__global__ void k_scan3() {
    int b = blockIdx.x, i = b * 256 + threadIdx.x;
    int o = g_off[i] + g_blksum[b];
    g_off[i] = o;
    g_cursor[i] = o;
}
__global__ void k_scatter(const int* __restrict__ e, int E) {
    int i = blockIdx.x * 256 + threadIdx.x;
    if (i < E) {
        int d = e[E + i];
        int p = atomicAdd(&g_cursor[d], 1);
        if (p < EMAX) g_csr[p] = e[i];
    }
}

// ---------------- K6: sector-resident softmax aggregate + pooling ----------
#define AGG_SMEM_F (PERSEC * HG + PERSEC + PERSEC + 8 * HG)
__global__ void __launch_bounds__(256) k_agg_sec(const float* __restrict__ b1) {
    extern __shared__ float smf[];
    float* sh1 = smf;                       // 256*64
    float* ssc = smf + PERSEC * HG;         // 256
    float* ssd = ssc + PERSEC;              // 256
    float* red = ssd + PERSEC;              // 8*64
    int s = blockIdx.x, base = s * PERSEC;
    int t = threadIdx.x, lane = t & 31, warp = t >> 5;
    for (int i = t; i < PERSEC * HG; i += 256) sh1[i] = g_h1[(size_t)base * HG + i];
    if (t < PERSEC) { ssc[t] = g_ssrc[base + t]; ssd[t] = g_sdst[base + t]; }
    __syncthreads();

    float bl0 = b1[lane], bl1 = b1[lane + 32];
    float pm0 = -3.4e38f, pm1 = -3.4e38f;
    for (int di = warp; di < PERSEC; di += 8) {
        int dst = base + di;
        float sd = ssd[di];
        float m = lrelu(ssc[di] + sd);
        float den = 1.f;
        float a0 = sh1[di * HG + lane], a1 = sh1[di * HG + lane + 32];
        int s0 = g_off[dst], e0 = g_off[dst + 1];
        for (int b2 = s0; b2 < e0; b2 += 32) {
            int p = b2 + lane;
            bool valid = p < e0;
            int srcl = valid ? (g_csr[p] - base) : 0;
            float ev = valid ? lrelu(ssc[srcl] + sd) : -3.4e38f;
            float cm = ev;
            for (int o = 16; o; o >>= 1)
                cm = fmaxf(cm, __shfl_xor_sync(0xffffffffu, cm, o));
            if (cm > m) {
                float f = __expf(m - cm);
                a0 *= f; a1 *= f; den *= f;
                m = cm;
            }
            int cnt = min(32, e0 - b2);
            int j = 0;
            for (; j + 4 <= cnt; j += 4) {
                int s0j = __shfl_sync(0xffffffffu, srcl, j);
                int s1j = __shfl_sync(0xffffffffu, srcl, j + 1);
                int s2j = __shfl_sync(0xffffffffu, srcl, j + 2);
                int s3j = __shfl_sync(0xffffffffu, srcl, j + 3);
                float e0j = __shfl_sync(0xffffffffu, ev, j);
                float e1j = __shfl_sync(0xffffffffu, ev, j + 1);
                float e2j = __shfl_sync(0xffffffffu, ev, j + 2);
                float e3j = __shfl_sync(0xffffffffu, ev, j + 3);
                float w0 = __expf(e0j - m), w1 = __expf(e1j - m);
                float w2 = __expf(e2j - m), w3 = __expf(e3j - m);
                den += (w0 + w1) + (w2 + w3);
                float h00 = sh1[s0j * HG + lane], h01 = sh1[s0j * HG + lane + 32];
                float h10 = sh1[s1j * HG + lane], h11 = sh1[s1j * HG + lane + 32];
                float h20 = sh1[s2j * HG + lane], h21 = sh1[s2j * HG + lane + 32];
                float h30 = sh1[s3j * HG + lane], h31 = sh1[s3j * HG + lane + 32];
                a0 = fmaf(w0, h00, a0); a1 = fmaf(w0, h01, a1);
                a0 = fmaf(w1, h10, a0); a1 = fmaf(w1, h11, a1);
                a0 = fmaf(w2, h20, a0); a1 = fmaf(w2, h21, a1);
                a0 = fmaf(w3, h30, a0); a1 = fmaf(w3, h31, a1);
            }
            for (; j < cnt; j++) {
                int sj = __shfl_sync(0xffffffffu, srcl, j);
                float ej = __shfl_sync(0xffffffffu, ev, j);
                float wj = __expf(ej - m);
                den += wj;
                a0 = fmaf(wj, sh1[sj * HG + lane], a0);
                a1 = fmaf(wj, sh1[sj * HG + lane + 32], a1);
            }
        }
        float inv = __fdividef(1.f, den + 1e-16f);
        float r0 = a0 * inv + bl0, r1 = a1 * inv + bl1;
        g_intra[(size_t)dst * HG + lane] = r0;
        g_intra[(size_t)dst * HG + lane + 32] = r1;
        pm0 = fmaxf(pm0, r0); pm1 = fmaxf(pm1, r1);
    }
    red[warp * HG + lane] = pm0;
    red[warp * HG + lane + 32] = pm1;
    __syncthreads();
    if (t < HG) {
        float mm = red[t];
#pragma unroll
        for (int w2 = 1; w2 < 8; w2++) mm = fmaxf(mm, red[w2 * HG + t]);
        g_pool[s * HG + t] = mm;
    }
}

// ---------------- K8: GAT2 on 64 sectors (dense, one block) ----------------
__global__ void k_gat2(const float* __restrict__ W2,
                       const float* __restrict__ a2s,
                       const float* __restrict__ a2d,
                       const float* __restrict__ b2) {
    __shared__ float W2s[HG * HG];
    __shared__ float h2s[64 * 68];
    __shared__ float ss[64], sd[64], as_s[64], ad_s[64];
    int t = threadIdx.x;
    for (int i = t; i < HG * HG; i += 256) W2s[i] = W2[i];
    if (t < 64) { as_s[t] = a2s[t]; ad_s[t] = a2d[t]; }
    __syncthreads();

    int i = t >> 2, q = t & 3;
    {
        float4 acc[4] = {make_float4(0,0,0,0), make_float4(0,0,0,0),
                         make_float4(0,0,0,0), make_float4(0,0,0,0)};
        for (int k = 0; k < HG; k++) {
            float x = g_pool[i * HG + k];
            const float* row = W2s + k * HG + q * 16;
#pragma unroll
            for (int u = 0; u < 4; u++) fma4(acc[u], x, ld4(row + 4 * u));
        }
#pragma unroll
        for (int u = 0; u < 4; u++) st4(h2s + i * 68 + q * 16 + 4 * u, acc[u]);
    }
    __syncthreads();
    if (t < 64) {
        float s1 = 0.f, s2 = 0.f;
        for (int k = 0; k < HG; k++) {
            float v = h2s[t * 68 + k];
            s1 += v * as_s[k]; s2 += v * ad_s[k];
        }
        ss[t] = s1; sd[t] = s2;
    }
    __syncthreads();
    {
        int wi = t >> 5, lane = t & 31;
        for (int dst = wi; dst < 64; dst += 8) {
            float e1 = lrelu(ss[lane] + sd[dst]);
            float e2 = lrelu(ss[lane + 32] + sd[dst]);
            float m = fmaxf(e1, e2);
            for (int o = 16; o; o >>= 1) m = fmaxf(m, __shfl_xor_sync(0xffffffffu, m, o));
            float w1 = __expf(e1 - m), w2 = __expf(e2 - m);
            float s = w1 + w2;
            for (int o = 16; o; o >>= 1) s += __shfl_xor_sync(0xffffffffu, s, o);
            float inv = 1.f / (s + 1e-16f);
            W2s[dst * 64 + lane] = w1 * inv;
            W2s[dst * 64 + lane + 32] = w2 * inv;
        }
    }
    __syncthreads();
    {
        int dst = i;
        float4 o[4] = {make_float4(0,0,0,0), make_float4(0,0,0,0),
                       make_float4(0,0,0,0), make_float4(0,0,0,0)};
        for (int src = 0; src < 64; src++) {
            float a = W2s[dst * 64 + src];
            const float* row = h2s + src * 68 + q * 16;
#pragma unroll
            for (int u = 0; u < 4; u++) fma4(o[u], a, ld4(row + 4 * u));
        }
#pragma unroll
        for (int u = 0; u < 4; u++) {
            int jb = q * 16 + 4 * u;
            float4 v = o[u];
            v.x += b2[jb]; v.y += b2[jb + 1]; v.z += b2[jb + 2]; v.w += b2[jb + 3];
            st4(g_sec + dst * HG + jb, v);
        }
    }
}

// ---------------- K9: HMMA fusion + logits ----------------
#define FUS_SMEM_U32 (WFF_U32 + 128 * 68 + 64 + 256 + 4 + 64)
__global__ void __launch_bounds__(256) k_fusion_mma(const float* __restrict__ fb,
                                                    const float* __restrict__ lw,
                                                    const float* __restrict__ lb,
                                                    float* __restrict__ out) {
    extern __shared__ unsigned smu[];
    unsigned* sWf = smu;                         // 12288
    float* fs = (float*)(smu + WFF_U32);         // 128*68
    float* ssec = fs + 128 * 68;                 // 64
    float* lws = ssec + 64;                      // 256
    float* lbs = lws + 256;                      // 4
    float* fbs = lbs + 4;                        // 64
    int t = threadIdx.x, lane = t & 31, warp = t >> 5;
    int c0 = blockIdx.x * 128;
    int sec = c0 >> 8;
    for (int i = t; i < WFF_U32; i += 256) sWf[i] = g_WfF[i];
    if (t < 64) {
        ssec[t] = g_sec[sec * HG + t];
        fbs[t] = fb[t];
    }
    if (t < 256) lws[t] = lw[t];
    if (t < 4) lbs[t] = lb[t];
    __syncthreads();

    int row0 = c0 + warp * 16 + (lane >> 2);
    int colq = 2 * (lane & 3);

    unsigned ah[12][4], al[12][4];
#pragma unroll
    for (int kt = 0; kt < 4; kt++) {
#pragma unroll
        for (int rh = 0; rh < 2; rh++) {
            const float* sp = g_seq + (size_t)(row0 + rh * 8) * HG + kt * 16 + colq;
            float2 v0 = *(const float2*)sp;
            float2 v1 = *(const float2*)(sp + 8);
            pack_hilo(v0.x, v0.y, ah[kt][rh], al[kt][rh]);
            pack_hilo(v1.x, v1.y, ah[kt][2 + rh], al[kt][2 + rh]);
        }
    }
#pragma unroll
    for (int kt = 0; kt < 4; kt++) {
        const float* sp = ssec + kt * 16 + colq;
        float2 v0 = *(const float2*)sp;
        float2 v1 = *(const float2*)(sp + 8);
        unsigned h0, l0v, h1, l1v;
        pack_hilo(v0.x, v0.y, h0, l0v);
        pack_hilo(v1.x, v1.y, h1, l1v);
        ah[4 + kt][0] = h0; ah[4 + kt][1] = h0;
        al[4 + kt][0] = l0v; al[4 + kt][1] = l0v;
        ah[4 + kt][2] = h1; ah[4 + kt][3] = h1;
        al[4 + kt][2] = l1v; al[4 + kt][3] = l1v;
    }
#pragma unroll
    for (int kt = 0; kt < 4; kt++) {
#pragma unroll
        for (int rh = 0; rh < 2; rh++) {
            const float* sp = g_intra + (size_t)(row0 + rh * 8) * HG + kt * 16 + colq;
            float2 v0 = *(const float2*)sp;
            float2 v1 = *(const float2*)(sp + 8);
            pack_hilo(v0.x, v0.y, ah[8 + kt][rh], al[8 + kt][rh]);
            pack_hilo(v1.x, v1.y, ah[8 + kt][2 + rh], al[8 + kt][2 + rh]);
        }
    }
    float D[8][4];
#pragma unroll
    for (int nt = 0; nt < 8; nt++) D[nt][0] = D[nt][1] = D[nt][2] = D[nt][3] = 0.f;
#pragma unroll
    for (int kt = 0; kt < 12; kt++) {
#pragma unroll
        for (int nt = 0; nt < 8; nt++) {
            const unsigned* bh = sWf + ((0 + kt) * 8 + nt) * 64 + lane * 2;
            const unsigned* bl = sWf + ((12 + kt) * 8 + nt) * 64 + lane * 2;
            unsigned b0 = bh[0], b1 = bh[1];
            mma16816(D[nt], ah[kt], b0, b1);
            mma16816(D[nt], al[kt], b0, b1);
            mma16816(D[nt], ah[kt], bl[0], bl[1]);
        }
    }
    int rowL = warp * 16 + (lane >> 2);
#pragma unroll
    for (int nt = 0; nt < 8; nt++) {
#pragma unroll
        for (int rh = 0; rh < 2; rh++) {
            int col = 8 * nt + colq;
            float v0 = fmaxf(D[nt][rh * 2] + fbs[col], 0.f);
            float v1 = fmaxf(D[nt][rh * 2 + 1] + fbs[col + 1], 0.f);
            *(float2*)(fs + (rowL + rh * 8) * 68 + col) = make_float2(v0, v1);
        }
    }
    __syncthreads();
    if (t < 128) {
        int c2 = c0 + t;
        float l0 = lbs[0], l1 = lbs[1], l2 = lbs[2], l3 = lbs[3];
        for (int k = 0; k < HG; k++) {
            float fv = fs[t * 68 + k];
            l0 = fmaf(fv, lws[k * 4 + 0], l0);
            l1 = fmaf(fv, lws[k * 4 + 1], l1);
            l2 = fmaf(fv, lws[k * 4 + 2], l2);
            l3 = fmaf(fv, lws[k * 4 + 3], l3);
        }
        float m = fmaxf(fmaxf(l0, l1), fmaxf(l2, l3));
        float e0 = __expf(l0 - m), e1 = __expf(l1 - m), e2 = __expf(l2 - m), e3 = __expf(l3 - m);
        float inv = 1.f / (e0 + e1 + e2 + e3);
        float p0 = e0 * inv, p1 = e1 * inv, p2 = e2 * inv, p3 = e3 * inv;
        float cA = p0, cB = cA + p1, cC = cB + p2, cD = cC + p3;
        const float EPS = 5e-8f, HI = 1.f - 5e-8f;
        float4 r;
        r.x = fminf(fmaxf(cA, EPS), HI);
        r.y = fminf(fmaxf(cB, EPS), HI);
        r.z = fminf(fmaxf(cC, EPS), HI);
        r.w = fminf(fmaxf(cD, EPS), HI);
        st4(out + (size_t)c2 * 4, r);
    }
}

// ---------------- launch ----------------
extern "C" void kernel_launch(void* const* d_in, const int* in_sizes, int n_in,
                              void* d_out, int out_size) {
    const float* daily = (const float*)d_in[0];
    const int* inner = (const int*)d_in[1];
    const float* gamma = (const float*)d_in[4];
    const float* beta = (const float*)d_in[5];
    const float* Wih = (const float*)d_in[6];
    const float* Whh = (const float*)d_in[7];
    const float* bih = (const float*)d_in[8];
    const float* bhh = (const float*)d_in[9];
    const float* h0 = (const float*)d_in[10];
    const float* W1 = (const float*)d_in[11];
    const float* a1s = (const float*)d_in[12];
    const float* a1d = (const float*)d_in[13];
    const float* b1 = (const float*)d_in[14];
    const float* W2 = (const float*)d_in[15];
    const float* a2s = (const float*)d_in[16];
    const float* a2d = (const float*)d_in[17];
    const float* b2 = (const float*)d_in[18];
    const float* Wf = (const float*)d_in[19];
    const float* fb = (const float*)d_in[20];
    const float* lw = (const float*)d_in[21];
    const float* lb = (const float*)d_in[22];
    float* out = (float*)d_out;
    int E = in_sizes[1] / 2;

    cudaFuncSetAttribute(k_gru_mma, cudaFuncAttributeMaxDynamicSharedMemorySize,
                         GRU_SMEM_U32 * 4);
    cudaFuncSetAttribute(k_agg_sec, cudaFuncAttributeMaxDynamicSharedMemorySize,
                         AGG_SMEM_F * 4);
    cudaFuncSetAttribute(k_fusion_mma, cudaFuncAttributeMaxDynamicSharedMemorySize,
                         FUS_SMEM_U32 * 4);

    k_bn_stats<<<dim3(WIN, 8), 256>>>(daily);
    k_bn_fin<<<2, 256>>>(gamma, beta);
    k_prep_bias<<<WIN, G3>>>(Wih, bih, bhh);
    k_prep_frag<<<(WFH_U32 + WFX_U32 + 255) / 256, 256>>>(Wih, Whh);
    k_prep_frag2<<<(W1F_U32 + WFF_U32 + 255) / 256, 256>>>(W1, Wf);
    k_gru_mma<<<NCOMP / 128, 256, GRU_SMEM_U32 * 4>>>(daily, h0);
    k_gat1_mma<<<NCOMP / 128, 256>>>(a1s, a1d);
    k_deg0<<<NCOMP / 256, 256>>>();
    k_deg<<<(E + 255) / 256, 256>>>(inner, E);
    k_scan1<<<NCOMP / 256, 256>>>();
    k_scan2<<<1, 32>>>(E);
    k_scan3<<<NCOMP / 256, 256>>>();
    k_scatter<<<(E + 255) / 256, 256>>>(inner, E);
    k_agg_sec<<<NSEC, 256, AGG_SMEM_F * 4>>>(b1);
    k_gat2<<<1, 256>>>(W2, a2s, a2d, b2);
    k_fusion_mma<<<NCOMP / 128, 256, FUS_SMEM_U32 * 4>>>(fb, lw, lb, out);
}

// round 8
// speedup vs baseline: 3.4351x; 1.1142x over previous
#include <cuda_runtime.h>
#include <cuda_bf16.h>
#include <cstdint>

#define NCOMP 16384
#define NSEC 64
#define PERSEC 256
#define WIN 32
#define DIN 16
#define HG 64
#define G3 192
#define EMAX 524288

// ---------------- scratch (device globals; no allocation) ----------------
__device__ float g_bnpartS[WIN * 8 * DIN];
__device__ float g_bnpartQ[WIN * 8 * DIN];
__device__ float g_scale[WIN * DIN];
__device__ float g_shift[WIN * DIN];
__device__ float g_bias[WIN * G3];
__device__ float g_bnh[64];
#define WFH_U32 (2 * 4 * 24 * 64)   // GRU Whh frags
#define WFX_U32 (2 * 24 * 64)       // GRU Wih frags
#define W1F_U32 (2 * 4 * 8 * 64)    // GAT1 W frags
#define WFF_U32 (2 * 12 * 8 * 64)   // fusion W frags
__device__ unsigned g_WhF[WFH_U32];
__device__ unsigned g_WxF[WFX_U32];
__device__ unsigned g_W1F[W1F_U32];
__device__ unsigned g_WfF[WFF_U32];
__device__ float g_seq[NCOMP * HG];
__device__ float g_h1[NCOMP * HG];
__device__ float g_ssrc[NCOMP];
__device__ float g_sdst[NCOMP];
__device__ float g_intra[NCOMP * HG];
__device__ float g_pool[NSEC * HG];
__device__ float g_sec[NSEC * HG];
__device__ int g_deg[NCOMP];
__device__ int g_off[NCOMP + 1];
__device__ int g_cursor[NCOMP];
__device__ int g_blksum[64];
__device__ int g_csr[EMAX];

// ---------------- helpers ----------------
__device__ __forceinline__ float4 ld4(const float* p) { return *(const float4*)p; }
__device__ __forceinline__ void st4(float* p, float4 v) { *(float4*)p = v; }
__device__ __forceinline__ void fma4(float4& a, float s, float4 b) {
    a.x = fmaf(s, b.x, a.x); a.y = fmaf(s, b.y, a.y);
    a.z = fmaf(s, b.z, a.z); a.w = fmaf(s, b.w, a.w);
}
__device__ __forceinline__ float lrelu(float v) { return v > 0.f ? v : 0.2f * v; }
__device__ __forceinline__ float tanh_apx(float x) {
    float y; asm("tanh.approx.f32 %0, %1;" : "=f"(y) : "f"(x)); return y;
}

__device__ __forceinline__ unsigned packbf(float v0, float v1) {
    unsigned r;
    asm("cvt.rn.bf16x2.f32 %0, %1, %2;" : "=r"(r) : "f"(v1), "f"(v0));
    return r;
}
__device__ __forceinline__ void pack_hilo(float v0, float v1, unsigned& hi, unsigned& lo) {
    unsigned hp = packbf(v0, v1);
    float h0 = __uint_as_float(hp << 16);
    float h1 = __uint_as_float(hp & 0xffff0000u);
    lo = packbf(v0 - h0, v1 - h1);
    hi = hp;
}
__device__ __forceinline__ void mma16816(float* d, const unsigned* a,
                                         unsigned b0, unsigned b1) {
    asm volatile(
        "mma.sync.aligned.m16n8k16.row.col.f32.bf16.bf16.f32 "
        "{%0,%1,%2,%3}, {%4,%5,%6,%7}, {%8,%9}, {%0,%1,%2,%3};"
        : "+f"(d[0]), "+f"(d[1]), "+f"(d[2]), "+f"(d[3])
        : "r"(a[0]), "r"(a[1]), "r"(a[2]), "r"(a[3]), "r"(b0), "r"(b1));
}

// ---------------- K1a: BN partial sums (grid WIN x 8, deterministic) --------
__global__ void k_bn_stats(const float* __restrict__ daily) {
    int w = blockIdx.x, by = blockIdx.y;
    int t = threadIdx.x, lane = t & 31, wid = t >> 5;
    float s[DIN], q[DIN];
#pragma unroll
    for (int d = 0; d < DIN; d++) { s[d] = 0.f; q[d] = 0.f; }
    const float4* base =
        (const float4*)(daily + ((size_t)w * NCOMP + by * 2048) * DIN);
    for (int n = t; n < 2048; n += 256) {
        float4 vv[4];
        vv[0] = base[n * 4 + 0]; vv[1] = base[n * 4 + 1];
        vv[2] = base[n * 4 + 2]; vv[3] = base[n * 4 + 3];
        const float* v = (const float*)vv;
#pragma unroll
        for (int d = 0; d < DIN; d++) { s[d] += v[d]; q[d] += v[d] * v[d]; }
    }
#pragma unroll
    for (int d = 0; d < DIN; d++) {
        for (int o = 16; o; o >>= 1) {
            s[d] += __shfl_down_sync(0xffffffffu, s[d], o);
            q[d] += __shfl_down_sync(0xffffffffu, q[d], o);
        }
    }
    __shared__ float S[8][DIN], Q[8][DIN];
    if (lane == 0) {
#pragma unroll
        for (int d = 0; d < DIN; d++) { S[wid][d] = s[d]; Q[wid][d] = q[d]; }
    }
    __syncthreads();
    if (t < DIN) {
        float ts = 0.f, tq = 0.f;
#pragma unroll
        for (int r = 0; r < 8; r++) { ts += S[r][t]; tq += Q[r][t]; }
        g_bnpartS[(w * 8 + t / DIN * 0 + by) * DIN + t] = ts;
        g_bnpartQ[(w * 8 + by) * DIN + t] = tq;
    }
}

// ---------------- K1b: finalize scale/shift + fused per-step biases ---------
__global__ void k_bn_prep(const float* __restrict__ gamma,
                          const float* __restrict__ beta,
                          const float* __restrict__ Wih,
                          const float* __restrict__ bih,
                          const float* __restrict__ bhh) {
    int w = blockIdx.x, j = threadIdx.x;
    __shared__ float sh_shift[DIN];
    if (j < DIN) {
        int f = w * DIN + j;
        float ts = 0.f, tq = 0.f;
#pragma unroll
        for (int by = 0; by < 8; by++) {
            ts += g_bnpartS[(w * 8 + by) * DIN + j];
            tq += g_bnpartQ[(w * 8 + by) * DIN + j];
        }
        float mu = ts * (1.f / (float)NCOMP);
        float var = tq * (1.f / (float)NCOMP) - mu * mu;
        float sc = gamma[f] * rsqrtf(var + 1e-5f);
        g_scale[f] = sc;
        float sh = beta[f] - mu * sc;
        g_shift[f] = sh;
        sh_shift[j] = sh;
    }
    __syncthreads();
    float acc = bih[j] + (j < 128 ? bhh[j] : 0.f);
#pragma unroll
    for (int d = 0; d < DIN; d++) acc += sh_shift[d] * Wih[d * G3 + j];
    g_bias[w * G3 + j] = acc;
    if (w == 0 && j < 64) g_bnh[j] = bhh[128 + j];
}

// ---------------- K2b: GRU fragment weights ----------------
__global__ void k_prep_frag(const float* __restrict__ Wih,
                            const float* __restrict__ Whh) {
    int id = blockIdx.x * 256 + threadIdx.x;
    if (id < WFH_U32) {
        int r = id & 1;
        int lane = (id >> 1) & 31;
        int q = id >> 6;
        int nt = q % 24, kt = (q / 24) % 4, s = q / 96;
        int k = kt * 16 + 2 * (lane & 3) + (r ? 8 : 0);
        int n = nt * 8 + (lane >> 2);
        float v0 = Whh[k * G3 + n], v1 = Whh[(k + 1) * G3 + n];
        unsigned hi, lo;
        pack_hilo(v0, v1, hi, lo);
        g_WhF[id] = s == 0 ? hi : lo;
        return;
    }
    int id2 = id - WFH_U32;
    if (id2 < WFX_U32) {
        int r = id2 & 1;
        int lane = (id2 >> 1) & 31;
        int q = id2 >> 6;
        int nt = q % 24, s = q / 24;
        int k = 2 * (lane & 3) + (r ? 8 : 0);
        int n = nt * 8 + (lane >> 2);
        float v0 = Wih[k * G3 + n], v1 = Wih[(k + 1) * G3 + n];
        unsigned hi, lo;
        pack_hilo(v0, v1, hi, lo);
        g_WxF[id2] = s == 0 ? hi : lo;
    }
}

// ---------------- K2c: GAT1 + fusion fragment weights ----------------
__global__ void k_prep_frag2(const float* __restrict__ W1,
                             const float* __restrict__ Wf) {
    int id = blockIdx.x * 256 + threadIdx.x;
    if (id < W1F_U32) {
        int r = id & 1, lane = (id >> 1) & 31, q = id >> 6;
        int nt = q % 8, kt = (q / 8) % 4, s = q / 32;
        int k = kt * 16 + 2 * (lane & 3) + (r ? 8 : 0);
        int n = nt * 8 + (lane >> 2);
        float v0 = W1[k * HG + n], v1 = W1[(k + 1) * HG + n];
        unsigned hi, lo;
        pack_hilo(v0, v1, hi, lo);
        g_W1F[id] = s ? lo : hi;
        return;
    }
    int i2 = id - W1F_U32;
    if (i2 < WFF_U32) {
        int r = i2 & 1, lane = (i2 >> 1) & 31, q = i2 >> 6;
        int nt = q % 8, kt = (q / 8) % 12, s = q / 96;
        int k = kt * 16 + 2 * (lane & 3) + (r ? 8 : 0);
        int n = nt * 8 + (lane >> 2);
        float v0 = Wf[k * HG + n], v1 = Wf[(k + 1) * HG + n];
        unsigned hi, lo;
        pack_hilo(v0, v1, hi, lo);
        g_WfF[i2] = s ? lo : hi;
    }
}

// ---------------- K3: HMMA GRU (148 blocks x 7 warps, tanh.approx) ----------
#define GRU_WPB 7
#define GRU_THR (GRU_WPB * 32)
#define GRU_SMEM_U32 (WFH_U32 + WFX_U32 + 6144 + 64 + 512)
__global__ void __launch_bounds__(GRU_THR) k_gru_mma(const float* __restrict__ daily,
                                                     const float* __restrict__ h0) {
    extern __shared__ unsigned smu[];
    unsigned* s_WhF = smu;
    unsigned* s_WxF = smu + WFH_U32;
    float* s_bias = (float*)(smu + WFH_U32 + WFX_U32);
    float* s_bnh = s_bias + 6144;
    float* s_scale = s_bnh + 64;
    int t = threadIdx.x, lane = t & 31, warp = t >> 5;

    for (int i = t; i < WFH_U32; i += GRU_THR) s_WhF[i] = g_WhF[i];
    for (int i = t; i < WFX_U32; i += GRU_THR) s_WxF[i] = g_WxF[i];
    for (int i = t; i < 6144; i += GRU_THR) s_bias[i] = g_bias[i];
    if (t < 64) s_bnh[t] = g_bnh[t];
    for (int i = t; i < 512; i += GRU_THR) s_scale[i] = g_scale[i];
    __syncthreads();

    int gw = blockIdx.x * GRU_WPB + warp;
    if (gw >= NCOMP / 16) return;
    int row0 = gw * 16 + (lane >> 2);
    int colb = (lane & 3) * 2;

    float h[32];
#pragma unroll
    for (int rh = 0; rh < 2; rh++) {
        const float* hp = h0 + (size_t)(row0 + rh * 8) * HG + colb;
#pragma unroll
        for (int m = 0; m < 8; m++) {
            float2 v = *(const float2*)(hp + 8 * m);
            h[rh * 16 + m * 2] = v.x;
            h[rh * 16 + m * 2 + 1] = v.y;
        }
    }

#pragma unroll 1
    for (int w = 0; w < WIN; w++) {
        unsigned ax_hi[4], ax_lo[4];
        {
            float sc0 = s_scale[w * 16 + colb], sc1 = s_scale[w * 16 + colb + 1];
            float sc8 = s_scale[w * 16 + colb + 8], sc9 = s_scale[w * 16 + colb + 9];
            const float* dw = daily + (size_t)w * NCOMP * DIN;
#pragma unroll
            for (int rh = 0; rh < 2; rh++) {
                const float* xp = dw + (size_t)(row0 + rh * 8) * DIN;
                float2 vlo = *(const float2*)(xp + colb);
                float2 vhi = *(const float2*)(xp + colb + 8);
                pack_hilo(vlo.x * sc0, vlo.y * sc1, ax_hi[rh], ax_lo[rh]);
                pack_hilo(vhi.x * sc8, vhi.y * sc9, ax_hi[2 + rh], ax_lo[2 + rh]);
            }
        }
        unsigned ah_hi[4][4], ah_lo[4][4];
#pragma unroll
        for (int kt = 0; kt < 4; kt++) {
#pragma unroll
            for (int rh = 0; rh < 2; rh++) {
                pack_hilo(h[rh * 16 + 4 * kt], h[rh * 16 + 4 * kt + 1],
                          ah_hi[kt][rh], ah_lo[kt][rh]);
                pack_hilo(h[rh * 16 + 4 * kt + 2], h[rh * 16 + 4 * kt + 3],
                          ah_hi[kt][2 + rh], ah_lo[kt][2 + rh]);
            }
        }
        float Dm[24][4], Dn[8][4];
#pragma unroll
        for (int nt = 0; nt < 24; nt++)
            Dm[nt][0] = Dm[nt][1] = Dm[nt][2] = Dm[nt][3] = 0.f;
#pragma unroll
        for (int nt = 0; nt < 8; nt++)
            Dn[nt][0] = Dn[nt][1] = Dn[nt][2] = Dn[nt][3] = 0.f;
#pragma unroll
        for (int nt = 0; nt < 24; nt++) {
            const unsigned* bh = s_WxF + nt * 64 + lane * 2;
            const unsigned* bl = s_WxF + (24 + nt) * 64 + lane * 2;
            unsigned b0 = bh[0], b1 = bh[1];
            mma16816(Dm[nt], ax_hi, b0, b1);
            mma16816(Dm[nt], ax_lo, b0, b1);
            mma16816(Dm[nt], ax_hi, bl[0], bl[1]);
        }
#pragma unroll
        for (int kt = 0; kt < 4; kt++) {
#pragma unroll
            for (int nt = 0; nt < 24; nt++) {
                const unsigned* bh = s_WhF + ((0 + kt) * 24 + nt) * 64 + lane * 2;
                const unsigned* bl = s_WhF + ((4 + kt) * 24 + nt) * 64 + lane * 2;
                float* D = (nt < 16) ? Dm[nt] : Dn[nt - 16];
                unsigned b0 = bh[0], b1 = bh[1];
                mma16816(D, ah_hi[kt], b0, b1);
                mma16816(D, ah_lo[kt], b0, b1);
                mma16816(D, ah_hi[kt], bl[0], bl[1]);
            }
        }
        const float* bw = s_bias + w * G3;
#pragma unroll
        for (int nt = 0; nt < 8; nt++) {
#pragma unroll
            for (int d = 0; d < 2; d++) {
                int j = 8 * nt + colb + d;
                float br = bw[j], bz = bw[64 + j], bn = bw[128 + j], bh2 = s_bnh[j];
#pragma unroll
                for (int rh = 0; rh < 2; rh++) {
                    int pos = rh * 2 + d;
                    float rp = Dm[nt][pos] + br;
                    float zp = Dm[8 + nt][pos] + bz;
                    float nip = Dm[16 + nt][pos] + bn;
                    float nhp = Dn[nt][pos] + bh2;
                    float r = fmaf(tanh_apx(0.5f * rp), 0.5f, 0.5f);
                    float z = fmaf(tanh_apx(0.5f * zp), 0.5f, 0.5f);
                    float nn = tanh_apx(fmaf(r, nhp, nip));
                    int hi = rh * 16 + nt * 2 + d;
                    h[hi] = fmaf(z, h[hi] - nn, nn);
                }
            }
        }
    }
#pragma unroll
    for (int rh = 0; rh < 2; rh++) {
        float* op = g_seq + (size_t)(row0 + rh * 8) * HG + colb;
#pragma unroll
        for (int m = 0; m < 8; m++)
            *(float2*)(op + 8 * m) =
                make_float2(h[rh * 16 + m * 2], h[rh * 16 + m * 2 + 1]);
    }
}

// ---------------- K4: HMMA GAT1 node transform + attention dots -------------
// (also zeroes g_deg for the CSR build that follows)
__global__ void __launch_bounds__(256) k_gat1_mma(const float* __restrict__ a1s,
                                                  const float* __restrict__ a1d) {
    __shared__ unsigned sW[W1F_U32];
    __shared__ float as_s[64], ad_s[64];
    int t = threadIdx.x, lane = t & 31, warp = t >> 5;
    int gt = blockIdx.x * 256 + t;
    if (gt < NCOMP) g_deg[gt] = 0;
    for (int i = t; i < W1F_U32; i += 256) sW[i] = g_W1F[i];
    if (t < 64) { as_s[t] = a1s[t]; ad_s[t] = a1d[t]; }
    __syncthreads();

    int row0 = blockIdx.x * 128 + warp * 16 + (lane >> 2);
    int colq = 2 * (lane & 3);

    unsigned ah[4][4], al[4][4];
#pragma unroll
    for (int kt = 0; kt < 4; kt++) {
#pragma unroll
        for (int rh = 0; rh < 2; rh++) {
            const float* sp = g_seq + (size_t)(row0 + rh * 8) * HG + kt * 16 + colq;
            float2 v0 = *(const float2*)sp;
            float2 v1 = *(const float2*)(sp + 8);
            pack_hilo(v0.x, v0.y, ah[kt][rh], al[kt][rh]);
            pack_hilo(v1.x, v1.y, ah[kt][2 + rh], al[kt][2 + rh]);
        }
    }
    float D[8][4];
#pragma unroll
    for (int nt = 0; nt < 8; nt++) D[nt][0] = D[nt][1] = D[nt][2] = D[nt][3] = 0.f;
#pragma unroll
    for (int kt = 0; kt < 4; kt++) {
#pragma unroll
        for (int nt = 0; nt < 8; nt++) {
            const unsigned* bh = sW + ((0 + kt) * 8 + nt) * 64 + lane * 2;
            const unsigned* bl = sW + ((4 + kt) * 8 + nt) * 64 + lane * 2;
            unsigned b0 = bh[0], b1 = bh[1];
            mma16816(D[nt], ah[kt], b0, b1);
            mma16816(D[nt], al[kt], b0, b1);
            mma16816(D[nt], ah[kt], bl[0], bl[1]);
        }
    }
    float ps[2] = {0.f, 0.f}, pd[2] = {0.f, 0.f};
#pragma unroll
    for (int nt = 0; nt < 8; nt++) {
#pragma unroll
        for (int rh = 0; rh < 2; rh++) {
            int col = 8 * nt + colq;
            float v0 = D[nt][rh * 2], v1 = D[nt][rh * 2 + 1];
            ps[rh] += v0 * as_s[col] + v1 * as_s[col + 1];
            pd[rh] += v0 * ad_s[col] + v1 * ad_s[col + 1];
            *(float2*)(g_h1 + (size_t)(row0 + rh * 8) * HG + col) =
                make_float2(v0, v1);
        }
    }
#pragma unroll
    for (int rh = 0; rh < 2; rh++) {
        ps[rh] += __shfl_xor_sync(0xffffffffu, ps[rh], 1);
        ps[rh] += __shfl_xor_sync(0xffffffffu, ps[rh], 2);
        pd[rh] += __shfl_xor_sync(0xffffffffu, pd[rh], 1);
        pd[rh] += __shfl_xor_sync(0xffffffffu, pd[rh], 2);
    }
    if ((lane & 3) == 0) {
        g_ssrc[row0] = ps[0]; g_ssrc[row0 + 8] = ps[1];
        g_sdst[row0] = pd[0]; g_sdst[row0 + 8] = pd[1];
    }
}

// ---------------- CSR build ----------------
__global__ void k_deg(const int* __restrict__ e, int E) {
    int i = blockIdx.x * 256 + threadIdx.x;
    if (i < E) atomicAdd(&g_deg[e[E + i]], 1);
}
__global__ void k_scan1() {
    __shared__ int s[256];
    int b = blockIdx.x, t = threadIdx.x, i = b * 256 + t;
    int d = g_deg[i];
    s[t] = d;
    __syncthreads();
    for (int o = 1; o < 256; o <<= 1) {
        int v = (t >= o) ? s[t - o] : 0;
        __syncthreads();
        s[t] += v;
        __syncthreads();
    }
    g_off[i] = s[t] - d;
    if (t == 255) g_blksum[b] = s[255];
}
__global__ void k_scan2(int E) {
    int lane = threadIdx.x & 31;
    int v0 = g_blksum[lane], v1 = g_blksum[32 + lane];
    int s0 = v0, s1 = v1;
    for (int o = 1; o < 32; o <<= 1) {
        int t0 = __shfl_up_sync(0xffffffffu, s0, o);
        int t1 = __shfl_up_sync(0xffffffffu, s1, o);
        if (lane >= o) { s0 += t0; s1 += t1; }
    }
    int tot0 = __shfl_sync(0xffffffffu, s0, 31);
    g_blksum[lane] = s0 - v0;
    g_blksum[32 + lane] = tot0 + s1 - v1;
    if (lane == 0) g_off[NCOMP] = E;
}
__global__ void k_scan3() {
    int b = blockIdx.x, i = b * 256 + threadIdx.x;
    int o = g_off[i] + g_blksum[b];
    g_off[i] = o;
    g_cursor[i] = o;
}
__global__ void k_scatter(const int* __restrict__ e, int E) {
    int i = blockIdx.x * 256 + threadIdx.x;
    if (i < E) {
        int d = e[E + i];
        int p = atomicAdd(&g_cursor[d], 1);
        if (p < EMAX) g_csr[p] = e[i];
    }
}

// ---------------- K6: sector-resident softmax aggregate + pooling ----------
#define AGG_SMEM_F (PERSEC * HG + PERSEC + PERSEC + 8 * HG)
__global__ void __launch_bounds__(256) k_agg_sec(const float* __restrict__ b1) {
    extern __shared__ float smf[];
    float* sh1 = smf;
    float* ssc = smf + PERSEC * HG;
    float* ssd = ssc + PERSEC;
    float* red = ssd + PERSEC;
    int s = blockIdx.x, base = s * PERSEC;
    int t = threadIdx.x, lane = t & 31, warp = t >> 5;
    for (int i = t; i < PERSEC * HG; i += 256) sh1[i] = g_h1[(size_t)base * HG + i];
    if (t < PERSEC) { ssc[t] = g_ssrc[base + t]; ssd[t] = g_sdst[base + t]; }
    __syncthreads();

    float bl0 = b1[lane], bl1 = b1[lane + 32];
    float pm0 = -3.4e38f, pm1 = -3.4e38f;
    for (int di = warp; di < PERSEC; di += 8) {
        int dst = base + di;
        float sd = ssd[di];
        float m = lrelu(ssc[di] + sd);
        float den = 1.f;
        float a0 = sh1[di * HG + lane], a1 = sh1[di * HG + lane + 32];
        int s0 = g_off[dst], e0 = g_off[dst + 1];
        for (int b2 = s0; b2 < e0; b2 += 32) {
            int p = b2 + lane;
            bool valid = p < e0;
            int srcl = valid ? (g_csr[p] - base) : 0;
            float ev = valid ? lrelu(ssc[srcl] + sd) : -3.4e38f;
            float cm = ev;
            for (int o = 16; o; o >>= 1)
                cm = fmaxf(cm, __shfl_xor_sync(0xffffffffu, cm, o));
            if (cm > m) {
                float f = __expf(m - cm);
                a0 *= f; a1 *= f; den *= f;
                m = cm;
            }
            int cnt = min(32, e0 - b2);
            int j = 0;
            for (; j + 4 <= cnt; j += 4) {
                int s0j = __shfl_sync(0xffffffffu, srcl, j);
                int s1j = __shfl_sync(0xffffffffu, srcl, j + 1);
                int s2j = __shfl_sync(0xffffffffu, srcl, j + 2);
                int s3j = __shfl_sync(0xffffffffu, srcl, j + 3);
                float e0j = __shfl_sync(0xffffffffu, ev, j);
                float e1j = __shfl_sync(0xffffffffu, ev, j + 1);
                float e2j = __shfl_sync(0xffffffffu, ev, j + 2);
                float e3j = __shfl_sync(0xffffffffu, ev, j + 3);
                float w0 = __expf(e0j - m), w1 = __expf(e1j - m);
                float w2 = __expf(e2j - m), w3 = __expf(e3j - m);
                den += (w0 + w1) + (w2 + w3);
                float h00 = sh1[s0j * HG + lane], h01 = sh1[s0j * HG + lane + 32];
                float h10 = sh1[s1j * HG + lane], h11 = sh1[s1j * HG + lane + 32];
                float h20 = sh1[s2j * HG + lane], h21 = sh1[s2j * HG + lane + 32];
                float h30 = sh1[s3j * HG + lane], h31 = sh1[s3j * HG + lane + 32];
                a0 = fmaf(w0, h00, a0); a1 = fmaf(w0, h01, a1);
                a0 = fmaf(w1, h10, a0); a1 = fmaf(w1, h11, a1);
                a0 = fmaf(w2, h20, a0); a1 = fmaf(w2, h21, a1);
                a0 = fmaf(w3, h30, a0); a1 = fmaf(w3, h31, a1);
            }
            for (; j < cnt; j++) {
                int sj = __shfl_sync(0xffffffffu, srcl, j);
                float ej = __shfl_sync(0xffffffffu, ev, j);
                float wj = __expf(ej - m);
                den += wj;
                a0 = fmaf(wj, sh1[sj * HG + lane], a0);
                a1 = fmaf(wj, sh1[sj * HG + lane + 32], a1);
            }
        }
        float inv = __fdividef(1.f, den + 1e-16f);
        float r0 = a0 * inv + bl0, r1 = a1 * inv + bl1;
        g_intra[(size_t)dst * HG + lane] = r0;
        g_intra[(size_t)dst * HG + lane + 32] = r1;
        pm0 = fmaxf(pm0, r0); pm1 = fmaxf(pm1, r1);
    }
    red[warp * HG + lane] = pm0;
    red[warp * HG + lane + 32] = pm1;
    __syncthreads();
    if (t < HG) {
        float mm = red[t];
#pragma unroll
        for (int w2 = 1; w2 < 8; w2++) mm = fmaxf(mm, red[w2 * HG + t]);
        g_pool[s * HG + t] = mm;
    }
}

// ---------------- K8: GAT2 on 64 sectors (dense, one block) ----------------
__global__ void k_gat2(const float* __restrict__ W2,
                       const float* __restrict__ a2s,
                       const float* __restrict__ a2d,
                       const float* __restrict__ b2) {
    __shared__ float W2s[HG * HG];
    __shared__ float h2s[64 * 68];
    __shared__ float ss[64], sd[64], as_s[64], ad_s[64];
    int t = threadIdx.x;
    for (int i = t; i < HG * HG; i += 256) W2s[i] = W2[i];
    if (t < 64) { as_s[t] = a2s[t]; ad_s[t] = a2d[t]; }
    __syncthreads();

    int i = t >> 2, q = t & 3;
    {
        float4 acc[4] = {make_float4(0,0,0,0), make_float4(0,0,0,0),
                         make_float4(0,0,0,0), make_float4(0,0,0,0)};
        for (int k = 0; k < HG; k++) {
            float x = g_pool[i * HG + k];
            const float* row = W2s + k * HG + q * 16;
#pragma unroll
            for (int u = 0; u < 4; u++) fma4(acc[u], x, ld4(row + 4 * u));
        }
#pragma unroll
        for (int u = 0; u < 4; u++) st4(h2s + i * 68 + q * 16 + 4 * u, acc[u]);
    }
    __syncthreads();
    if (t < 64) {
        float s1 = 0.f, s2 = 0.f;
        for (int k = 0; k < HG; k++) {
            float v = h2s[t * 68 + k];
            s1 += v * as_s[k]; s2 += v * ad_s[k];
        }
        ss[t] = s1; sd[t] = s2;
    }
    __syncthreads();
    {
        int wi = t >> 5, lane = t & 31;
        for (int dst = wi; dst < 64; dst += 8) {
            float e1 = lrelu(ss[lane] + sd[dst]);
            float e2 = lrelu(ss[lane + 32] + sd[dst]);
            float m = fmaxf(e1, e2);
            for (int o = 16; o; o >>= 1) m = fmaxf(m, __shfl_xor_sync(0xffffffffu, m, o));
            float w1 = __expf(e1 - m), w2 = __expf(e2 - m);
            float s = w1 + w2;
            for (int o = 16; o; o >>= 1) s += __shfl_xor_sync(0xffffffffu, s, o);
            float inv = 1.f / (s + 1e-16f);
            W2s[dst * 64 + lane] = w1 * inv;
            W2s[dst * 64 + lane + 32] = w2 * inv;
        }
    }
    __syncthreads();
    {
        int dst = i;
        float4 o[4] = {make_float4(0,0,0,0), make_float4(0,0,0,0),
                       make_float4(0,0,0,0), make_float4(0,0,0,0)};
        for (int src = 0; src < 64; src++) {
            float a = W2s[dst * 64 + src];
            const float* row = h2s + src * 68 + q * 16;
#pragma unroll
            for (int u = 0; u < 4; u++) fma4(o[u], a, ld4(row + 4 * u));
        }
#pragma unroll
        for (int u = 0; u < 4; u++) {
            int jb = q * 16 + 4 * u;
            float4 v = o[u];
            v.x += b2[jb]; v.y += b2[jb + 1]; v.z += b2[jb + 2]; v.w += b2[jb + 3];
            st4(g_sec + dst * HG + jb, v);
        }
    }
}

// ---------------- K9: HMMA fusion + logits ----------------
#define FUS_SMEM_U32 (WFF_U32 + 128 * 68 + 64 + 256 + 4 + 64)
__global__ void __launch_bounds__(256) k_fusion_mma(const float* __restrict__ fb,
                                                    const float* __restrict__ lw,
                                                    const float* __restrict__ lb,
                                                    float* __restrict__ out) {
    extern __shared__ unsigned smu[];
    unsigned* sWf = smu;
    float* fs = (float*)(smu + WFF_U32);
    float* ssec = fs + 128 * 68;
    float* lws = ssec + 64;
    float* lbs = lws + 256;
    float* fbs = lbs + 4;
    int t = threadIdx.x, lane = t & 31, warp = t >> 5;
    int c0 = blockIdx.x * 128;
    int sec = c0 >> 8;
    for (int i = t; i < WFF_U32; i += 256) sWf[i] = g_WfF[i];
    if (t < 64) {
        ssec[t] = g_sec[sec * HG + t];
        fbs[t] = fb[t];
    }
    if (t < 256) lws[t] = lw[t];
    if (t < 4) lbs[t] = lb[t];
    __syncthreads();

    int row0 = c0 + warp * 16 + (lane >> 2);
    int colq = 2 * (lane & 3);

    unsigned ah[12][4], al[12][4];
#pragma unroll
    for (int kt = 0; kt < 4; kt++) {
#pragma unroll
        for (int rh = 0; rh < 2; rh++) {
            const float* sp = g_seq + (size_t)(row0 + rh * 8) * HG + kt * 16 + colq;
            float2 v0 = *(const float2*)sp;
            float2 v1 = *(const float2*)(sp + 8);
            pack_hilo(v0.x, v0.y, ah[kt][rh], al[kt][rh]);
            pack_hilo(v1.x, v1.y, ah[kt][2 + rh], al[kt][2 + rh]);
        }
    }
#pragma unroll
    for (int kt = 0; kt < 4; kt++) {
        const float* sp = ssec + kt * 16 + colq;
        float2 v0 = *(const float2*)sp;
        float2 v1 = *(const float2*)(sp + 8);
        unsigned h0v, l0v, h1v, l1v;
        pack_hilo(v0.x, v0.y, h0v, l0v);
        pack_hilo(v1.x, v1.y, h1v, l1v);
        ah[4 + kt][0] = h0v; ah[4 + kt][1] = h0v;
        al[4 + kt][0] = l0v; al[4 + kt][1] = l0v;
        ah[4 + kt][2] = h1v; ah[4 + kt][3] = h1v;
        al[4 + kt][2] = l1v; al[4 + kt][3] = l1v;
    }
#pragma unroll
    for (int kt = 0; kt < 4; kt++) {
#pragma unroll
        for (int rh = 0; rh < 2; rh++) {
            const float* sp = g_intra + (size_t)(row0 + rh * 8) * HG + kt * 16 + colq;
            float2 v0 = *(const float2*)sp;
            float2 v1 = *(const float2*)(sp + 8);
            pack_hilo(v0.x, v0.y, ah[8 + kt][rh], al[8 + kt][rh]);
            pack_hilo(v1.x, v1.y, ah[8 + kt][2 + rh], al[8 + kt][2 + rh]);
        }
    }
    float D[8][4];
#pragma unroll
    for (int nt = 0; nt < 8; nt++) D[nt][0] = D[nt][1] = D[nt][2] = D[nt][3] = 0.f;
#pragma unroll
    for (int kt = 0; kt < 12; kt++) {
#pragma unroll
        for (int nt = 0; nt < 8; nt++) {
            const unsigned* bh = sWf + ((0 + kt) * 8 + nt) * 64 + lane * 2;
            const unsigned* bl = sWf + ((12 + kt) * 8 + nt) * 64 + lane * 2;
            unsigned b0 = bh[0], b1 = bh[1];
            mma16816(D[nt], ah[kt], b0, b1);
            mma16816(D[nt], al[kt], b0, b1);
            mma16816(D[nt], ah[kt], bl[0], bl[1]);
        }
    }
    int rowL = warp * 16 + (lane >> 2);
#pragma unroll
    for (int nt = 0; nt < 8; nt++) {
#pragma unroll
        for (int rh = 0; rh < 2; rh++) {
            int col = 8 * nt + colq;
            float v0 = fmaxf(D[nt][rh * 2] + fbs[col], 0.f);
            float v1 = fmaxf(D[nt][rh * 2 + 1] + fbs[col + 1], 0.f);
            *(float2*)(fs + (rowL + rh * 8) * 68 + col) = make_float2(v0, v1);
        }
    }
    __syncthreads();
    if (t < 128) {
        int c2 = c0 + t;
        float l0 = lbs[0], l1 = lbs[1], l2 = lbs[2], l3 = lbs[3];
        for (int k = 0; k < HG; k++) {
            float fv = fs[t * 68 + k];
            l0 = fmaf(fv, lws[k * 4 + 0], l0);
            l1 = fmaf(fv, lws[k * 4 + 1], l1);
            l2 = fmaf(fv, lws[k * 4 + 2], l2);
            l3 = fmaf(fv, lws[k * 4 + 3], l3);
        }
        float m = fmaxf(fmaxf(l0, l1), fmaxf(l2, l3));
        float e0 = __expf(l0 - m), e1 = __expf(l1 - m), e2 = __expf(l2 - m), e3 = __expf(l3 - m);
        float inv = 1.f / (e0 + e1 + e2 + e3);
        float p0 = e0 * inv, p1 = e1 * inv, p2 = e2 * inv, p3 = e3 * inv;
        float cA = p0, cB = cA + p1, cC = cB + p2, cD = cC + p3;
        const float EPS = 5e-8f, HI = 1.f - 5e-8f;
        float4 r;
        r.x = fminf(fmaxf(cA, EPS), HI);
        r.y = fminf(fmaxf(cB, EPS), HI);
        r.z = fminf(fmaxf(cC, EPS), HI);
        r.w = fminf(fmaxf(cD, EPS), HI);
        st4(out + (size_t)c2 * 4, r);
    }
}

// ---------------- launch ----------------
extern "C" void kernel_launch(void* const* d_in, const int* in_sizes, int n_in,
                              void* d_out, int out_size) {
    const float* daily = (const float*)d_in[0];
    const int* inner = (const int*)d_in[1];
    const float* gamma = (const float*)d_in[4];
    const float* beta = (const float*)d_in[5];
    const float* Wih = (const float*)d_in[6];
    const float* Whh = (const float*)d_in[7];
    const float* bih = (const float*)d_in[8];
    const float* bhh = (const float*)d_in[9];
    const float* h0 = (const float*)d_in[10];
    const float* W1 = (const float*)d_in[11];
    const float* a1s = (const float*)d_in[12];
    const float* a1d = (const float*)d_in[13];
    const float* b1 = (const float*)d_in[14];
    const float* W2 = (const float*)d_in[15];
    const float* a2s = (const float*)d_in[16];
    const float* a2d = (const float*)d_in[17];
    const float* b2 = (const float*)d_in[18];
    const float* Wf = (const float*)d_in[19];
    const float* fb = (const float*)d_in[20];
    const float* lw = (const float*)d_in[21];
    const float* lb = (const float*)d_in[22];
    float* out = (float*)d_out;
    int E = in_sizes[1] / 2;
    int nGruBlk = (NCOMP / 16 + GRU_WPB - 1) / GRU_WPB;

    cudaFuncSetAttribute(k_gru_mma, cudaFuncAttributeMaxDynamicSharedMemorySize,
                         GRU_SMEM_U32 * 4);
    cudaFuncSetAttribute(k_agg_sec, cudaFuncAttributeMaxDynamicSharedMemorySize,
                         AGG_SMEM_F * 4);
    cudaFuncSetAttribute(k_fusion_mma, cudaFuncAttributeMaxDynamicSharedMemorySize,
                         FUS_SMEM_U32 * 4);

    k_bn_stats<<<dim3(WIN, 8), 256>>>(daily);
    k_bn_prep<<<WIN, G3>>>(gamma, beta, Wih, bih, bhh);
    k_prep_frag<<<(WFH_U32 + WFX_U32 + 255) / 256, 256>>>(Wih, Whh);
    k_prep_frag2<<<(W1F_U32 + WFF_U32 + 255) / 256, 256>>>(W1, Wf);
    k_gru_mma<<<nGruBlk, GRU_THR, GRU_SMEM_U32 * 4>>>(daily, h0);
    k_gat1_mma<<<NCOMP / 128, 256>>>(a1s, a1d);
    k_deg<<<(E + 255) / 256, 256>>>(inner, E);
    k_scan1<<<NCOMP / 256, 256>>>();
    k_scan2<<<1, 32>>>(E);
    k_scan3<<<NCOMP / 256, 256>>>();
    k_scatter<<<(E + 255) / 256, 256>>>(inner, E);
    k_agg_sec<<<NSEC, 256, AGG_SMEM_F * 4>>>(b1);
    k_gat2<<<1, 256>>>(W2, a2s, a2d, b2);
    k_fusion_mma<<<NCOMP / 128, 256, FUS_SMEM_U32 * 4>>>(fb, lw, lb, out);
}